// round 7
// baseline (speedup 1.0000x reference)
#include <cuda_runtime.h>
#include <math.h>

// ---------------- problem constants ----------------
#define C_CLS   1000
#define DIMG    2048
#define DATT    312
#define HH      128
#define BB      2048
#define THRESH  0.76604444311897803f   // cos(40 deg)
#define TEMP    32.0f

typedef unsigned long long ull;

// ---------------- scratch (device globals; no allocation allowed) -------
__device__ float g_proto_red[C_CLS * DATT];        // [1000,312]
__device__ float g_gn[C_CLS * HH];                 // [1000,128]
__device__ float g_attn[C_CLS * C_CLS];            // [1000,1000]
__device__ float g_M[C_CLS * HH];                  // [1000,128]
__device__ float g_proto_h[C_CLS * HH];            // [1000,128]
__device__ float g_img_h[BB * HH];                 // [2048,128]
__device__ float g_scr_a[16 * C_CLS * DATT];       // proto_red / proto_h partials
__device__ float g_scr_b[16 * BB * HH];            // img_h partials
__device__ float g_scr_m[4 * C_CLS * HH];          // M partials

// ---------------- packed f32x2 helpers ----------------
__device__ __forceinline__ ull pk2(float x, float y) {
    ull r;
    asm("mov.b64 %0, {%1, %2};" : "=l"(r) : "r"(__float_as_uint(x)), "r"(__float_as_uint(y)));
    return r;
}
__device__ __forceinline__ ull fma2(ull a, ull b, ull c) {
    ull d;
    asm("fma.rn.f32x2 %0, %1, %2, %3;" : "=l"(d) : "l"(a), "l"(b), "l"(c));
    return d;
}
__device__ __forceinline__ ull add2(ull a, ull b) {
    ull d;
    asm("add.rn.f32x2 %0, %1, %2;" : "=l"(d) : "l"(a), "l"(b));
    return d;
}
__device__ __forceinline__ void upk2(ull v, float& x, float& y) {
    unsigned lo, hi;
    asm("mov.b64 {%0, %1}, %2;" : "=r"(lo), "=r"(hi) : "l"(v));
    x = __uint_as_float(lo); y = __uint_as_float(hi);
}

// ---------------- big GEMM: C = A[MxK] @ B[KxN], BM=128 BN=128 BK=16 ----
// 256 threads, 8x8/thread. Non-duplicated smem (2 B/lane-FFMA2: crossbar and
// fma pipe balanced); A duplicated into (a,a) pairs via MOV on the alu pipe.
// Ping-pong smem double buffering, one barrier per k-tile. Split-K partials.
__global__ void __launch_bounds__(256)
gemm256(const float* __restrict__ A, const float* __restrict__ B,
        float* __restrict__ Cpart, int M, int N, int K, int Ks)
{
    __shared__ __align__(16) float As[2][16][132];
    __shared__ __align__(16) float Bs[2][16][132];
    const int tid = threadIdx.x;
    const int z = blockIdx.z;
    const int kbeg = z * Ks;                        // Ks multiple of 4
    const int kend = min(K, kbeg + Ks);
    const int row0 = blockIdx.y * 128;
    const int col0 = blockIdx.x * 128;
    const int tx = tid & 15;        // cols: tx*8
    const int ty = tid >> 4;        // rows: ty*8
    const int akq = tid & 3;        // A loader k-quad
    const int ar  = tid >> 2;       // A loader row (0..63, +64 second)
    const int br  = tid >> 4;       // B loader k-row (0..15)
    const int bcq = tid & 15;       // B loader col-octet

    ull acc[8][4];
    #pragma unroll
    for (int r = 0; r < 8; r++)
        #pragma unroll
        for (int j = 0; j < 4; j++) acc[r][j] = 0ull;

    const int arow0 = min(row0 + ar,      M - 1);
    const int arow1 = min(row0 + ar + 64, M - 1);
    const float* Ar0 = A + (size_t)arow0 * K;
    const float* Ar1 = A + (size_t)arow1 * K;
    const bool colFast = (col0 + 127 < N);

    float4 sa0, sa1, sb0, sb1;   // staging registers

    auto loadTile = [&](int kb) {
        const int ka = kb + akq * 4;
        if (ka + 3 < kend) {
            sa0 = *(const float4*)(Ar0 + ka);
            sa1 = *(const float4*)(Ar1 + ka);
        } else {
            sa0.x = (ka+0 < kend) ? Ar0[ka+0] : 0.f;
            sa0.y = (ka+1 < kend) ? Ar0[ka+1] : 0.f;
            sa0.z = (ka+2 < kend) ? Ar0[ka+2] : 0.f;
            sa0.w = (ka+3 < kend) ? Ar0[ka+3] : 0.f;
            sa1.x = (ka+0 < kend) ? Ar1[ka+0] : 0.f;
            sa1.y = (ka+1 < kend) ? Ar1[ka+1] : 0.f;
            sa1.z = (ka+2 < kend) ? Ar1[ka+2] : 0.f;
            sa1.w = (ka+3 < kend) ? Ar1[ka+3] : 0.f;
        }
        const int kb2 = kb + br;
        const int bc = col0 + bcq * 8;
        sb0 = make_float4(0.f, 0.f, 0.f, 0.f);
        sb1 = sb0;
        if (kb2 < kend) {
            const float* Bp = B + (size_t)kb2 * N;
            if (colFast) {
                sb0 = *(const float4*)(Bp + bc);
                sb1 = *(const float4*)(Bp + bc + 4);
            } else {
                if (bc+0 < N) sb0.x = Bp[bc+0];
                if (bc+1 < N) sb0.y = Bp[bc+1];
                if (bc+2 < N) sb0.z = Bp[bc+2];
                if (bc+3 < N) sb0.w = Bp[bc+3];
                if (bc+4 < N) sb1.x = Bp[bc+4];
                if (bc+5 < N) sb1.y = Bp[bc+5];
                if (bc+6 < N) sb1.z = Bp[bc+6];
                if (bc+7 < N) sb1.w = Bp[bc+7];
            }
        }
    };
    auto storeTile = [&](int p) {
        As[p][akq*4+0][ar]    = sa0.x;
        As[p][akq*4+1][ar]    = sa0.y;
        As[p][akq*4+2][ar]    = sa0.z;
        As[p][akq*4+3][ar]    = sa0.w;
        As[p][akq*4+0][ar+64] = sa1.x;
        As[p][akq*4+1][ar+64] = sa1.y;
        As[p][akq*4+2][ar+64] = sa1.z;
        As[p][akq*4+3][ar+64] = sa1.w;
        *(float4*)&Bs[p][br][bcq*8]     = sb0;
        *(float4*)&Bs[p][br][bcq*8 + 4] = sb1;
    };

    loadTile(kbeg);
    storeTile(0);
    __syncthreads();

    int p = 0;
    for (int k0 = kbeg; k0 < kend; k0 += 16) {
        const bool hasNext = (k0 + 16) < kend;
        if (hasNext) loadTile(k0 + 16);       // LDG overlapped with compute

        #pragma unroll
        for (int kk = 0; kk < 16; kk++) {
            float4 af0 = *(const float4*)&As[p][kk][ty*8];
            float4 af1 = *(const float4*)&As[p][kk][ty*8 + 4];
            ulonglong2 b01 = *(const ulonglong2*)&Bs[p][kk][tx*8];
            ulonglong2 b23 = *(const ulonglong2*)&Bs[p][kk][tx*8 + 4];
            ull ad;
            ad = pk2(af0.x, af0.x);
            acc[0][0]=fma2(ad,b01.x,acc[0][0]); acc[0][1]=fma2(ad,b01.y,acc[0][1]);
            acc[0][2]=fma2(ad,b23.x,acc[0][2]); acc[0][3]=fma2(ad,b23.y,acc[0][3]);
            ad = pk2(af0.y, af0.y);
            acc[1][0]=fma2(ad,b01.x,acc[1][0]); acc[1][1]=fma2(ad,b01.y,acc[1][1]);
            acc[1][2]=fma2(ad,b23.x,acc[1][2]); acc[1][3]=fma2(ad,b23.y,acc[1][3]);
            ad = pk2(af0.z, af0.z);
            acc[2][0]=fma2(ad,b01.x,acc[2][0]); acc[2][1]=fma2(ad,b01.y,acc[2][1]);
            acc[2][2]=fma2(ad,b23.x,acc[2][2]); acc[2][3]=fma2(ad,b23.y,acc[2][3]);
            ad = pk2(af0.w, af0.w);
            acc[3][0]=fma2(ad,b01.x,acc[3][0]); acc[3][1]=fma2(ad,b01.y,acc[3][1]);
            acc[3][2]=fma2(ad,b23.x,acc[3][2]); acc[3][3]=fma2(ad,b23.y,acc[3][3]);
            ad = pk2(af1.x, af1.x);
            acc[4][0]=fma2(ad,b01.x,acc[4][0]); acc[4][1]=fma2(ad,b01.y,acc[4][1]);
            acc[4][2]=fma2(ad,b23.x,acc[4][2]); acc[4][3]=fma2(ad,b23.y,acc[4][3]);
            ad = pk2(af1.y, af1.y);
            acc[5][0]=fma2(ad,b01.x,acc[5][0]); acc[5][1]=fma2(ad,b01.y,acc[5][1]);
            acc[5][2]=fma2(ad,b23.x,acc[5][2]); acc[5][3]=fma2(ad,b23.y,acc[5][3]);
            ad = pk2(af1.z, af1.z);
            acc[6][0]=fma2(ad,b01.x,acc[6][0]); acc[6][1]=fma2(ad,b01.y,acc[6][1]);
            acc[6][2]=fma2(ad,b23.x,acc[6][2]); acc[6][3]=fma2(ad,b23.y,acc[6][3]);
            ad = pk2(af1.w, af1.w);
            acc[7][0]=fma2(ad,b01.x,acc[7][0]); acc[7][1]=fma2(ad,b01.y,acc[7][1]);
            acc[7][2]=fma2(ad,b23.x,acc[7][2]); acc[7][3]=fma2(ad,b23.y,acc[7][3]);
        }
        if (hasNext) {
            storeTile(p ^ 1);                 // write OTHER buffer: no race
            __syncthreads();                  // one barrier per tile
            p ^= 1;
        }
    }

    float* Co = Cpart + (size_t)z * M * N;
    #pragma unroll
    for (int r = 0; r < 8; r++) {
        const int gr = row0 + ty*8 + r;
        if (gr >= M) continue;
        float c[8];
        upk2(acc[r][0], c[0], c[1]);
        upk2(acc[r][1], c[2], c[3]);
        upk2(acc[r][2], c[4], c[5]);
        upk2(acc[r][3], c[6], c[7]);
        const int gc = col0 + tx*8;
        if (gc + 7 < N) {
            *(float4*)&Co[(size_t)gr * N + gc]     = make_float4(c[0], c[1], c[2], c[3]);
            *(float4*)&Co[(size_t)gr * N + gc + 4] = make_float4(c[4], c[5], c[6], c[7]);
        } else {
            #pragma unroll
            for (int j = 0; j < 8; j++)
                if (gc + j < N) Co[(size_t)gr * N + gc + j] = c[j];
        }
    }
}

// ---------------- reduce split-K partials (+optional bias), any S -------
__global__ void reduce_k(float* __restrict__ out, const float* __restrict__ part,
                         int lenf4, int S, const float* __restrict__ bias, int N)
{
    int i = blockIdx.x * blockDim.x + threadIdx.x;
    if (i >= lenf4) return;
    const float4* p = (const float4*)part;
    float4 a0 = make_float4(0.f,0.f,0.f,0.f), a1 = a0, a2 = a0, a3 = a0;
    int z = 0;
    for (; z + 4 <= S; z += 4) {
        float4 t0 = p[(size_t)(z+0) * lenf4 + i];
        float4 t1 = p[(size_t)(z+1) * lenf4 + i];
        float4 t2 = p[(size_t)(z+2) * lenf4 + i];
        float4 t3 = p[(size_t)(z+3) * lenf4 + i];
        a0.x += t0.x; a0.y += t0.y; a0.z += t0.z; a0.w += t0.w;
        a1.x += t1.x; a1.y += t1.y; a1.z += t1.z; a1.w += t1.w;
        a2.x += t2.x; a2.y += t2.y; a2.z += t2.z; a2.w += t2.w;
        a3.x += t3.x; a3.y += t3.y; a3.z += t3.z; a3.w += t3.w;
    }
    for (; z < S; z++) {
        float4 t = p[(size_t)z * lenf4 + i];
        a0.x += t.x; a0.y += t.y; a0.z += t.z; a0.w += t.w;
    }
    float4 acc = make_float4(a0.x + a1.x + a2.x + a3.x,
                             a0.y + a1.y + a2.y + a3.y,
                             a0.z + a1.z + a2.z + a3.z,
                             a0.w + a1.w + a2.w + a3.w);
    if (bias) {
        int col = (i * 4) % N;      // N % 4 == 0 for all uses
        acc.x += bias[col+0]; acc.y += bias[col+1];
        acc.z += bias[col+2]; acc.w += bias[col+3];
    }
    ((float4*)out)[i] = acc;
}

// ---------------- gn = normalize_rows(attributes @ att_g) ----------------
__global__ void gn_kernel(const float* __restrict__ attrs,
                          const float* __restrict__ att_g,
                          float* __restrict__ gn) {
    __shared__ float s_attr[8][DATT];
    __shared__ float s_red[8][4];
    const int c0 = blockIdx.x * 8;
    const int t = threadIdx.x;       // 128
    const int lane = t & 31, warp = t >> 5;

    for (int i = t; i < 8 * DATT; i += 128) {
        int r = i / DATT, k = i - r * DATT;
        s_attr[r][k] = attrs[(size_t)(c0 + r) * DATT + k];
    }
    __syncthreads();

    float acc[8] = {0.f,0.f,0.f,0.f,0.f,0.f,0.f,0.f};
    for (int k = 0; k < DATT; k++) {
        float w = att_g[(size_t)k * HH + t];
        #pragma unroll
        for (int r = 0; r < 8; r++) acc[r] = fmaf(s_attr[r][k], w, acc[r]);
    }
    #pragma unroll
    for (int r = 0; r < 8; r++) {
        float sq = acc[r] * acc[r];
        #pragma unroll
        for (int o = 16; o; o >>= 1) sq += __shfl_xor_sync(0xffffffffu, sq, o);
        if (lane == 0) s_red[r][warp] = sq;
    }
    __syncthreads();
    #pragma unroll
    for (int r = 0; r < 8; r++) {
        float tot = s_red[r][0] + s_red[r][1] + s_red[r][2] + s_red[r][3];
        float inv = 1.f / fmaxf(sqrtf(tot), 1e-12f);
        gn[(size_t)(c0 + r) * HH + t] = acc[r] * inv;
    }
}

// ---------------- sim = gn @ gn^T, masked+scaled in epilogue ------------
__global__ void sim_kernel(const float* __restrict__ gn, float* __restrict__ out)
{
    __shared__ __align__(16) float As2[16][140];
    __shared__ __align__(16) float Bs[16][68];
    const int tid = threadIdx.x;
    const int row0 = blockIdx.y * 64;
    const int col0 = blockIdx.x * 64;
    const int tx = tid & 15, ty = tid >> 4;
    const int ar = tid >> 2, akq = tid & 3;

    const float* Arp = gn + (size_t)min(row0 + ar, C_CLS - 1) * HH;
    const float* Brp = gn + (size_t)min(col0 + ar, C_CLS - 1) * HH;

    ull acc[4][2];
    #pragma unroll
    for (int r = 0; r < 4; r++) { acc[r][0] = 0ull; acc[r][1] = 0ull; }

    for (int k0 = 0; k0 < HH; k0 += 16) {
        float4 av = *(const float4*)(Arp + k0 + akq*4);
        float4 bv = *(const float4*)(Brp + k0 + akq*4);
        *(float2*)&As2[akq*4+0][2*ar] = make_float2(av.x, av.x);
        *(float2*)&As2[akq*4+1][2*ar] = make_float2(av.y, av.y);
        *(float2*)&As2[akq*4+2][2*ar] = make_float2(av.z, av.z);
        *(float2*)&As2[akq*4+3][2*ar] = make_float2(av.w, av.w);
        Bs[akq*4+0][ar] = bv.x; Bs[akq*4+1][ar] = bv.y;
        Bs[akq*4+2][ar] = bv.z; Bs[akq*4+3][ar] = bv.w;
        __syncthreads();
        #pragma unroll
        for (int kk = 0; kk < 16; kk++) {
            ulonglong2 bq  = *(const ulonglong2*)&Bs[kk][tx*4];
            ulonglong2 a01 = *(const ulonglong2*)&As2[kk][ty*8];
            ulonglong2 a23 = *(const ulonglong2*)&As2[kk][ty*8+4];
            acc[0][0]=fma2(a01.x,bq.x,acc[0][0]); acc[0][1]=fma2(a01.x,bq.y,acc[0][1]);
            acc[1][0]=fma2(a01.y,bq.x,acc[1][0]); acc[1][1]=fma2(a01.y,bq.y,acc[1][1]);
            acc[2][0]=fma2(a23.x,bq.x,acc[2][0]); acc[2][1]=fma2(a23.x,bq.y,acc[2][1]);
            acc[3][0]=fma2(a23.y,bq.x,acc[3][0]); acc[3][1]=fma2(a23.y,bq.y,acc[3][1]);
        }
        __syncthreads();
    }

    #pragma unroll
    for (int r = 0; r < 4; r++) {
        const int gr = row0 + ty*4 + r;
        if (gr >= C_CLS) continue;
        float c[4];
        upk2(acc[r][0], c[0], c[1]);
        upk2(acc[r][1], c[2], c[3]);
        #pragma unroll
        for (int j = 0; j < 4; j++) {
            const int gc = col0 + tx*4 + j;
            if (gc >= C_CLS) continue;
            float s = c[j];
            out[(size_t)gr * C_CLS + gc] = (s > THRESH) ? s * TEMP : -1e30f;
        }
    }
}

// ---------------- row softmax (in place, values pre-masked+scaled) ------
__global__ void softmax_kernel(float* __restrict__ attn)
{
    __shared__ float s_red[8];
    const int t = threadIdx.x, lane = t & 31, warp = t >> 5;
    float* row = attn + (size_t)blockIdx.x * C_CLS;

    float v[4];
    float m = -1e30f;
    #pragma unroll
    for (int i = 0; i < 4; i++) {
        int c = t + i * 256;
        v[i] = (c < C_CLS) ? row[c] : -1e30f;
        m = fmaxf(m, v[i]);
    }
    #pragma unroll
    for (int o = 16; o; o >>= 1) m = fmaxf(m, __shfl_xor_sync(0xffffffffu, m, o));
    if (lane == 0) s_red[warp] = m;
    __syncthreads();
    m = s_red[0];
    #pragma unroll
    for (int w = 1; w < 8; w++) m = fmaxf(m, s_red[w]);
    __syncthreads();

    float sum = 0.f;
    #pragma unroll
    for (int i = 0; i < 4; i++) {
        float e = (v[i] > -1e29f) ? __expf(v[i] - m) : 0.f;
        v[i] = e;
        sum += e;
    }
    #pragma unroll
    for (int o = 16; o; o >>= 1) sum += __shfl_xor_sync(0xffffffffu, sum, o);
    if (lane == 0) s_red[warp] = sum;
    __syncthreads();
    float tot = 0.f;
    #pragma unroll
    for (int w = 0; w < 8; w++) tot += s_red[w];
    float inv = 1.f / tot;
    #pragma unroll
    for (int i = 0; i < 4; i++) {
        int c = t + i * 256;
        if (c < C_CLS) row[c] = v[i] * inv;
    }
}

// ---------------- relation MLP: out[b,c] = fc_b + sum_h relu(a+p)*w -----
__global__ void relation_kernel(const float* __restrict__ img_h,
                                const float* __restrict__ proto_h,
                                const float* __restrict__ fc_w,
                                const float* __restrict__ fc_b,
                                float* __restrict__ out)
{
    __shared__ __align__(16) float s_a2[64][136];  // [h][2*b] duplicated
    __shared__ __align__(16) float s_p[64][68];    // [h][c]
    __shared__ __align__(16) float s_w2[2 * HH];   // duplicated weights
    const int tid = threadIdx.x;
    const int b0 = blockIdx.y * 64;
    const int c0 = blockIdx.x * 64;
    const int tx = tid & 15;        // c: tx*4
    const int ty = tid >> 4;        // b: ty*4
    const int bl = tid >> 2;        // loader row (0..63)
    const int hq = tid & 3;         // loader h-quad group

    if (tid < HH) { float w = fc_w[tid]; s_w2[2*tid] = w; s_w2[2*tid+1] = w; }

    ull acc[4][2];
    #pragma unroll
    for (int i = 0; i < 4; i++) { acc[i][0] = 0ull; acc[i][1] = 0ull; }

    const float* arow = img_h   + (size_t)(b0 + bl) * HH;
    const float* prow = proto_h + (size_t)min(c0 + bl, C_CLS - 1) * HH;

    for (int h0 = 0; h0 < HH; h0 += 64) {
        #pragma unroll
        for (int it = 0; it < 4; it++) {
            const int hh = (hq + 4*it) * 4;
            float4 va = *(const float4*)(arow + h0 + hh);
            float4 vp = *(const float4*)(prow + h0 + hh);
            *(float2*)&s_a2[hh+0][2*bl] = make_float2(va.x, va.x);
            *(float2*)&s_a2[hh+1][2*bl] = make_float2(va.y, va.y);
            *(float2*)&s_a2[hh+2][2*bl] = make_float2(va.z, va.z);
            *(float2*)&s_a2[hh+3][2*bl] = make_float2(va.w, va.w);
            s_p[hh+0][bl] = vp.x; s_p[hh+1][bl] = vp.y;
            s_p[hh+2][bl] = vp.z; s_p[hh+3][bl] = vp.w;
        }
        __syncthreads();
        #pragma unroll 4
        for (int hh = 0; hh < 64; hh++) {
            ull w2 = *(const ull*)&s_w2[2*(h0 + hh)];
            ulonglong2 aA = *(const ulonglong2*)&s_a2[hh][ty*8];
            ulonglong2 aB = *(const ulonglong2*)&s_a2[hh][ty*8+4];
            ulonglong2 pv = *(const ulonglong2*)&s_p[hh][tx*4];
            ull av[4] = {aA.x, aA.y, aB.x, aB.y};
            #pragma unroll
            for (int i = 0; i < 4; i++) {
                #pragma unroll
                for (int jp = 0; jp < 2; jp++) {
                    ull t = add2(av[i], jp ? pv.y : pv.x);
                    float t0, t1;
                    upk2(t, t0, t1);
                    t = pk2(fmaxf(t0, 0.f), fmaxf(t1, 0.f));
                    acc[i][jp] = fma2(t, w2, acc[i][jp]);
                }
            }
        }
        __syncthreads();
    }

    const float bias = fc_b[0];
    #pragma unroll
    for (int i = 0; i < 4; i++) {
        const int b = b0 + ty*4 + i;
        float c[4];
        upk2(acc[i][0], c[0], c[1]);
        upk2(acc[i][1], c[2], c[3]);
        const int cc = c0 + tx*4;
        if (cc + 3 < C_CLS) {
            float4 v = make_float4(c[0] + bias, c[1] + bias, c[2] + bias, c[3] + bias);
            *(float4*)&out[(size_t)b * C_CLS + cc] = v;
        } else {
            #pragma unroll
            for (int j = 0; j < 4; j++)
                if (cc + j < C_CLS) out[(size_t)b * C_CLS + cc + j] = c[j] + bias;
        }
    }
}

// ---------------- host launch ----------------
extern "C" void kernel_launch(void* const* d_in, const int* in_sizes, int n_in,
                              void* d_out, int out_size) {
    const float* image_feats = (const float*)d_in[0];  // [2048,2048]
    const float* img_proto   = (const float*)d_in[1];  // [1000,2048]
    const float* attributes  = (const float*)d_in[2];  // [1000,312]
    const float* att_g   = (const float*)d_in[4];      // [312,128]
    const float* slim_w  = (const float*)d_in[5];      // [2048,312]
    const float* slim_b  = (const float*)d_in[6];      // [312]
    const float* img_w   = (const float*)d_in[7];      // [2048,128]
    const float* proto_w = (const float*)d_in[8];      // [624,128]
    const float* proto_b = (const float*)d_in[9];      // [1,128]
    const float* fc_w    = (const float*)d_in[10];     // [128,1]
    const float* fc_b    = (const float*)d_in[11];     // [1]
    float* out = (float*)d_out;

    float *proto_red, *gnp, *attnp, *Mp, *proto_hp, *img_hp, *scrA, *scrB, *scrM;
    cudaGetSymbolAddress((void**)&proto_red, g_proto_red);
    cudaGetSymbolAddress((void**)&gnp,       g_gn);
    cudaGetSymbolAddress((void**)&attnp,     g_attn);
    cudaGetSymbolAddress((void**)&Mp,        g_M);
    cudaGetSymbolAddress((void**)&proto_hp,  g_proto_h);
    cudaGetSymbolAddress((void**)&img_hp,    g_img_h);
    cudaGetSymbolAddress((void**)&scrA,      g_scr_a);
    cudaGetSymbolAddress((void**)&scrB,      g_scr_b);
    cudaGetSymbolAddress((void**)&scrM,      g_scr_m);

    static cudaStream_t s1 = nullptr, s2 = nullptr, s3 = nullptr;
    static cudaEvent_t ev0 = nullptr, ev1 = nullptr, ev2 = nullptr, ev3 = nullptr;
    if (!s1) {
        cudaStreamCreateWithFlags(&s1, cudaStreamNonBlocking);
        cudaStreamCreateWithFlags(&s2, cudaStreamNonBlocking);
        cudaStreamCreateWithFlags(&s3, cudaStreamNonBlocking);
        cudaEventCreateWithFlags(&ev0, cudaEventDisableTiming);
        cudaEventCreateWithFlags(&ev1, cudaEventDisableTiming);
        cudaEventCreateWithFlags(&ev2, cudaEventDisableTiming);
        cudaEventCreateWithFlags(&ev3, cudaEventDisableTiming);
    }
    cudaStream_t s0 = 0;

    // fork
    cudaEventRecord(ev0, s0);
    cudaStreamWaitEvent(s1, ev0, 0);
    cudaStreamWaitEvent(s2, ev0, 0);
    cudaStreamWaitEvent(s3, ev0, 0);

    // ---- chain C (s1): gn -> sim -> softmax --------------------------------
    gn_kernel<<<C_CLS / 8, 128, 0, s1>>>(attributes, att_g, gnp);
    sim_kernel<<<dim3(16, 16), 256, 0, s1>>>(gnp, attnp);
    softmax_kernel<<<C_CLS, 256, 0, s1>>>(attnp);
    cudaEventRecord(ev1, s1);

    // ---- chain A (s2): img_h (split-K 16) ----------------------------------
    gemm256<<<dim3(1, 16, 16), 256, 0, s2>>>(image_feats, img_w, scrB,
                                             BB, HH, DIMG, 128);
    reduce_k<<<(BB*HH/4 + 255)/256, 256, 0, s2>>>(img_hp, scrB, BB*HH/4, 16, nullptr, HH);
    cudaEventRecord(ev2, s2);

    // ---- chain D (s3): M_top = attributes @ proto_w[0:312] (slices 0,1) ----
    gemm256<<<dim3(1, 8, 2), 256, 0, s3>>>(attributes, proto_w, scrM,
                                           C_CLS, HH, DATT, 156);
    cudaEventRecord(ev3, s3);

    // ---- chain B (s0): proto_red -> M_bot -> M -> proto_h -> relation ------
    gemm256<<<dim3(3, 8, 8), 256, 0, s0>>>(img_proto, slim_w, scrA,
                                           C_CLS, DATT, DIMG, 256);
    reduce_k<<<(C_CLS*DATT/4 + 255)/256, 256, 0, s0>>>(proto_red, scrA, C_CLS*DATT/4, 8, slim_b, DATT);
    // M_bot partials into slices 2,3
    gemm256<<<dim3(1, 8, 2), 256, 0, s0>>>(proto_red, proto_w + (size_t)DATT * HH,
                                           scrM + 2 * (size_t)C_CLS * HH,
                                           C_CLS, HH, DATT, 156);
    // M = sum(4 slices) + proto_b
    cudaStreamWaitEvent(s0, ev3, 0);
    reduce_k<<<(C_CLS*HH/4 + 255)/256, 256, 0, s0>>>(Mp, scrM, C_CLS*HH/4, 4, proto_b, HH);

    // proto_h = attn @ M (split-K 16; proto_b folded via softmax row-sum = 1)
    cudaStreamWaitEvent(s0, ev1, 0);
    gemm256<<<dim3(1, 8, 16), 256, 0, s0>>>(attnp, Mp, scrA, C_CLS, HH, C_CLS, 64);
    reduce_k<<<(C_CLS*HH/4 + 255)/256, 256, 0, s0>>>(proto_hp, scrA, C_CLS*HH/4, 16, nullptr, HH);

    // ---- join: relation ----------------------------------------------------
    cudaStreamWaitEvent(s0, ev2, 0);
    relation_kernel<<<dim3(16, 32), 256, 0, s0>>>(img_hp, proto_hp, fc_w, fc_b, out);
}

// round 9
// speedup vs baseline: 1.0910x; 1.0910x over previous
#include <cuda_runtime.h>
#include <math.h>

// ---------------- problem constants ----------------
#define C_CLS   1000
#define DIMG    2048
#define DATT    312
#define HH      128
#define BB      2048
#define THRESH  0.76604444311897803f   // cos(40 deg)
#define TEMP    32.0f

typedef unsigned long long ull;

// ---------------- scratch (device globals; no allocation allowed) -------
__device__ float g_proto_red[C_CLS * DATT];        // [1000,312]
__device__ float g_gn[C_CLS * HH];                 // [1000,128]
__device__ float g_attn[C_CLS * C_CLS];            // [1000,1000]
__device__ float g_M[C_CLS * HH];                  // [1000,128]
__device__ float g_proto_h[C_CLS * HH];            // [1000,128]
__device__ float g_img_h[BB * HH];                 // [2048,128]
__device__ float g_scr_a[32 * C_CLS * HH + 16 * C_CLS * DATT]; // split-K partials
__device__ float g_scr_b[16 * BB * HH];            // img_h partials
__device__ float g_scr_m[8 * C_CLS * HH];          // M partials

// ---------------- packed f32x2 helpers ----------------
__device__ __forceinline__ ull pk2(float x, float y) {
    ull r;
    asm("mov.b64 %0, {%1, %2};" : "=l"(r) : "r"(__float_as_uint(x)), "r"(__float_as_uint(y)));
    return r;
}
__device__ __forceinline__ ull fma2(ull a, ull b, ull c) {
    ull d;
    asm("fma.rn.f32x2 %0, %1, %2, %3;" : "=l"(d) : "l"(a), "l"(b), "l"(c));
    return d;
}
__device__ __forceinline__ ull add2(ull a, ull b) {
    ull d;
    asm("add.rn.f32x2 %0, %1, %2;" : "=l"(d) : "l"(a), "l"(b));
    return d;
}
__device__ __forceinline__ void upk2(ull v, float& x, float& y) {
    unsigned lo, hi;
    asm("mov.b64 {%0, %1}, %2;" : "=r"(lo), "=r"(hi) : "l"(v));
    x = __uint_as_float(lo); y = __uint_as_float(hi);
}
// packed relu: unpack -> 2x FMNMX (alu pipe) -> repack (movs mostly elided)
__device__ __forceinline__ ull relu2(ull v) {
    float a, b;
    upk2(v, a, b);
    return pk2(fmaxf(a, 0.f), fmaxf(b, 0.f));
}

// ---------------- big GEMM: C = A[MxK] @ B[KxN], BM=128 BN=128 BK=16 ----
// 256 threads, 8x8/thread, FFMA2 inner loop, ping-pong smem, split-K.
__global__ void __launch_bounds__(256)
gemm256(const float* __restrict__ A, const float* __restrict__ B,
        float* __restrict__ Cpart, int M, int N, int K, int Ks)
{
    __shared__ __align__(16) float As[2][16][132];
    __shared__ __align__(16) float Bs[2][16][132];
    const int tid = threadIdx.x;
    const int z = blockIdx.z;
    const int kbeg = z * Ks;                        // Ks multiple of 4
    const int kend = min(K, kbeg + Ks);
    const int row0 = blockIdx.y * 128;
    const int col0 = blockIdx.x * 128;
    const int tx = tid & 15;        // cols: tx*8
    const int ty = tid >> 4;        // rows: ty*8
    const int akq = tid & 3;        // A loader k-quad
    const int ar  = tid >> 2;       // A loader row (0..63, +64 second)
    const int br  = tid >> 4;       // B loader k-row (0..15)
    const int bcq = tid & 15;       // B loader col-octet

    ull acc[8][4];
    #pragma unroll
    for (int r = 0; r < 8; r++)
        #pragma unroll
        for (int j = 0; j < 4; j++) acc[r][j] = 0ull;

    const int arow0 = min(row0 + ar,      M - 1);
    const int arow1 = min(row0 + ar + 64, M - 1);
    const float* Ar0 = A + (size_t)arow0 * K;
    const float* Ar1 = A + (size_t)arow1 * K;
    const bool colFast = (col0 + 127 < N);

    float4 sa0, sa1, sb0, sb1;   // staging registers

    auto loadTile = [&](int kb) {
        const int ka = kb + akq * 4;
        if (ka + 3 < kend) {
            sa0 = *(const float4*)(Ar0 + ka);
            sa1 = *(const float4*)(Ar1 + ka);
        } else {
            sa0.x = (ka+0 < kend) ? Ar0[ka+0] : 0.f;
            sa0.y = (ka+1 < kend) ? Ar0[ka+1] : 0.f;
            sa0.z = (ka+2 < kend) ? Ar0[ka+2] : 0.f;
            sa0.w = (ka+3 < kend) ? Ar0[ka+3] : 0.f;
            sa1.x = (ka+0 < kend) ? Ar1[ka+0] : 0.f;
            sa1.y = (ka+1 < kend) ? Ar1[ka+1] : 0.f;
            sa1.z = (ka+2 < kend) ? Ar1[ka+2] : 0.f;
            sa1.w = (ka+3 < kend) ? Ar1[ka+3] : 0.f;
        }
        const int kb2 = kb + br;
        const int bc = col0 + bcq * 8;
        sb0 = make_float4(0.f, 0.f, 0.f, 0.f);
        sb1 = sb0;
        if (kb2 < kend) {
            const float* Bp = B + (size_t)kb2 * N;
            if (colFast) {
                sb0 = *(const float4*)(Bp + bc);
                sb1 = *(const float4*)(Bp + bc + 4);
            } else {
                if (bc+0 < N) sb0.x = Bp[bc+0];
                if (bc+1 < N) sb0.y = Bp[bc+1];
                if (bc+2 < N) sb0.z = Bp[bc+2];
                if (bc+3 < N) sb0.w = Bp[bc+3];
                if (bc+4 < N) sb1.x = Bp[bc+4];
                if (bc+5 < N) sb1.y = Bp[bc+5];
                if (bc+6 < N) sb1.z = Bp[bc+6];
                if (bc+7 < N) sb1.w = Bp[bc+7];
            }
        }
    };
    auto storeTile = [&](int p) {
        As[p][akq*4+0][ar]    = sa0.x;
        As[p][akq*4+1][ar]    = sa0.y;
        As[p][akq*4+2][ar]    = sa0.z;
        As[p][akq*4+3][ar]    = sa0.w;
        As[p][akq*4+0][ar+64] = sa1.x;
        As[p][akq*4+1][ar+64] = sa1.y;
        As[p][akq*4+2][ar+64] = sa1.z;
        As[p][akq*4+3][ar+64] = sa1.w;
        *(float4*)&Bs[p][br][bcq*8]     = sb0;
        *(float4*)&Bs[p][br][bcq*8 + 4] = sb1;
    };

    loadTile(kbeg);
    storeTile(0);
    __syncthreads();

    int p = 0;
    for (int k0 = kbeg; k0 < kend; k0 += 16) {
        const bool hasNext = (k0 + 16) < kend;
        if (hasNext) loadTile(k0 + 16);       // LDG overlapped with compute

        #pragma unroll
        for (int kk = 0; kk < 16; kk++) {
            float4 af0 = *(const float4*)&As[p][kk][ty*8];
            float4 af1 = *(const float4*)&As[p][kk][ty*8 + 4];
            ulonglong2 b01 = *(const ulonglong2*)&Bs[p][kk][tx*8];
            ulonglong2 b23 = *(const ulonglong2*)&Bs[p][kk][tx*8 + 4];
            ull ad;
            ad = pk2(af0.x, af0.x);
            acc[0][0]=fma2(ad,b01.x,acc[0][0]); acc[0][1]=fma2(ad,b01.y,acc[0][1]);
            acc[0][2]=fma2(ad,b23.x,acc[0][2]); acc[0][3]=fma2(ad,b23.y,acc[0][3]);
            ad = pk2(af0.y, af0.y);
            acc[1][0]=fma2(ad,b01.x,acc[1][0]); acc[1][1]=fma2(ad,b01.y,acc[1][1]);
            acc[1][2]=fma2(ad,b23.x,acc[1][2]); acc[1][3]=fma2(ad,b23.y,acc[1][3]);
            ad = pk2(af0.z, af0.z);
            acc[2][0]=fma2(ad,b01.x,acc[2][0]); acc[2][1]=fma2(ad,b01.y,acc[2][1]);
            acc[2][2]=fma2(ad,b23.x,acc[2][2]); acc[2][3]=fma2(ad,b23.y,acc[2][3]);
            ad = pk2(af0.w, af0.w);
            acc[3][0]=fma2(ad,b01.x,acc[3][0]); acc[3][1]=fma2(ad,b01.y,acc[3][1]);
            acc[3][2]=fma2(ad,b23.x,acc[3][2]); acc[3][3]=fma2(ad,b23.y,acc[3][3]);
            ad = pk2(af1.x, af1.x);
            acc[4][0]=fma2(ad,b01.x,acc[4][0]); acc[4][1]=fma2(ad,b01.y,acc[4][1]);
            acc[4][2]=fma2(ad,b23.x,acc[4][2]); acc[4][3]=fma2(ad,b23.y,acc[4][3]);
            ad = pk2(af1.y, af1.y);
            acc[5][0]=fma2(ad,b01.x,acc[5][0]); acc[5][1]=fma2(ad,b01.y,acc[5][1]);
            acc[5][2]=fma2(ad,b23.x,acc[5][2]); acc[5][3]=fma2(ad,b23.y,acc[5][3]);
            ad = pk2(af1.z, af1.z);
            acc[6][0]=fma2(ad,b01.x,acc[6][0]); acc[6][1]=fma2(ad,b01.y,acc[6][1]);
            acc[6][2]=fma2(ad,b23.x,acc[6][2]); acc[6][3]=fma2(ad,b23.y,acc[6][3]);
            ad = pk2(af1.w, af1.w);
            acc[7][0]=fma2(ad,b01.x,acc[7][0]); acc[7][1]=fma2(ad,b01.y,acc[7][1]);
            acc[7][2]=fma2(ad,b23.x,acc[7][2]); acc[7][3]=fma2(ad,b23.y,acc[7][3]);
        }
        if (hasNext) {
            storeTile(p ^ 1);                 // write OTHER buffer: no race
            __syncthreads();                  // one barrier per tile
            p ^= 1;
        }
    }

    float* Co = Cpart + (size_t)z * M * N;
    #pragma unroll
    for (int r = 0; r < 8; r++) {
        const int gr = row0 + ty*8 + r;
        if (gr >= M) continue;
        float c[8];
        upk2(acc[r][0], c[0], c[1]);
        upk2(acc[r][1], c[2], c[3]);
        upk2(acc[r][2], c[4], c[5]);
        upk2(acc[r][3], c[6], c[7]);
        const int gc = col0 + tx*8;
        if (gc + 7 < N) {
            *(float4*)&Co[(size_t)gr * N + gc]     = make_float4(c[0], c[1], c[2], c[3]);
            *(float4*)&Co[(size_t)gr * N + gc + 4] = make_float4(c[4], c[5], c[6], c[7]);
        } else {
            #pragma unroll
            for (int j = 0; j < 8; j++)
                if (gc + j < N) Co[(size_t)gr * N + gc + j] = c[j];
        }
    }
}

// ---------------- reduce split-K partials (+optional bias), any S -------
__global__ void reduce_k(float* __restrict__ out, const float* __restrict__ part,
                         int lenf4, int S, const float* __restrict__ bias, int N)
{
    int i = blockIdx.x * blockDim.x + threadIdx.x;
    if (i >= lenf4) return;
    const float4* p = (const float4*)part;
    float4 a0 = make_float4(0.f,0.f,0.f,0.f), a1 = a0, a2 = a0, a3 = a0;
    int z = 0;
    for (; z + 4 <= S; z += 4) {
        float4 t0 = p[(size_t)(z+0) * lenf4 + i];
        float4 t1 = p[(size_t)(z+1) * lenf4 + i];
        float4 t2 = p[(size_t)(z+2) * lenf4 + i];
        float4 t3 = p[(size_t)(z+3) * lenf4 + i];
        a0.x += t0.x; a0.y += t0.y; a0.z += t0.z; a0.w += t0.w;
        a1.x += t1.x; a1.y += t1.y; a1.z += t1.z; a1.w += t1.w;
        a2.x += t2.x; a2.y += t2.y; a2.z += t2.z; a2.w += t2.w;
        a3.x += t3.x; a3.y += t3.y; a3.z += t3.z; a3.w += t3.w;
    }
    for (; z < S; z++) {
        float4 t = p[(size_t)z * lenf4 + i];
        a0.x += t.x; a0.y += t.y; a0.z += t.z; a0.w += t.w;
    }
    float4 acc = make_float4(a0.x + a1.x + a2.x + a3.x,
                             a0.y + a1.y + a2.y + a3.y,
                             a0.z + a1.z + a2.z + a3.z,
                             a0.w + a1.w + a2.w + a3.w);
    if (bias) {
        int col = (i * 4) % N;      // N % 4 == 0 for all uses
        acc.x += bias[col+0]; acc.y += bias[col+1];
        acc.z += bias[col+2]; acc.w += bias[col+3];
    }
    ((float4*)out)[i] = acc;
}

// ---------------- gn = normalize_rows(attributes @ att_g) ----------------
__global__ void gn_kernel(const float* __restrict__ attrs,
                          const float* __restrict__ att_g,
                          float* __restrict__ gn) {
    __shared__ float s_attr[8][DATT];
    __shared__ float s_red[8][4];
    const int c0 = blockIdx.x * 8;
    const int t = threadIdx.x;       // 128
    const int lane = t & 31, warp = t >> 5;

    for (int i = t; i < 8 * DATT; i += 128) {
        int r = i / DATT, k = i - r * DATT;
        s_attr[r][k] = attrs[(size_t)(c0 + r) * DATT + k];
    }
    __syncthreads();

    float acc[8] = {0.f,0.f,0.f,0.f,0.f,0.f,0.f,0.f};
    for (int k = 0; k < DATT; k++) {
        float w = att_g[(size_t)k * HH + t];
        #pragma unroll
        for (int r = 0; r < 8; r++) acc[r] = fmaf(s_attr[r][k], w, acc[r]);
    }
    #pragma unroll
    for (int r = 0; r < 8; r++) {
        float sq = acc[r] * acc[r];
        #pragma unroll
        for (int o = 16; o; o >>= 1) sq += __shfl_xor_sync(0xffffffffu, sq, o);
        if (lane == 0) s_red[r][warp] = sq;
    }
    __syncthreads();
    #pragma unroll
    for (int r = 0; r < 8; r++) {
        float tot = s_red[r][0] + s_red[r][1] + s_red[r][2] + s_red[r][3];
        float inv = 1.f / fmaxf(sqrtf(tot), 1e-12f);
        gn[(size_t)(c0 + r) * HH + t] = acc[r] * inv;
    }
}

// ---------------- sim = gn @ gn^T, masked+scaled in epilogue ------------
__global__ void sim_kernel(const float* __restrict__ gn, float* __restrict__ out)
{
    __shared__ __align__(16) float As2[16][140];
    __shared__ __align__(16) float Bs[16][68];
    const int tid = threadIdx.x;
    const int row0 = blockIdx.y * 64;
    const int col0 = blockIdx.x * 64;
    const int tx = tid & 15, ty = tid >> 4;
    const int ar = tid >> 2, akq = tid & 3;

    const float* Arp = gn + (size_t)min(row0 + ar, C_CLS - 1) * HH;
    const float* Brp = gn + (size_t)min(col0 + ar, C_CLS - 1) * HH;

    ull acc[4][2];
    #pragma unroll
    for (int r = 0; r < 4; r++) { acc[r][0] = 0ull; acc[r][1] = 0ull; }

    for (int k0 = 0; k0 < HH; k0 += 16) {
        float4 av = *(const float4*)(Arp + k0 + akq*4);
        float4 bv = *(const float4*)(Brp + k0 + akq*4);
        *(float2*)&As2[akq*4+0][2*ar] = make_float2(av.x, av.x);
        *(float2*)&As2[akq*4+1][2*ar] = make_float2(av.y, av.y);
        *(float2*)&As2[akq*4+2][2*ar] = make_float2(av.z, av.z);
        *(float2*)&As2[akq*4+3][2*ar] = make_float2(av.w, av.w);
        Bs[akq*4+0][ar] = bv.x; Bs[akq*4+1][ar] = bv.y;
        Bs[akq*4+2][ar] = bv.z; Bs[akq*4+3][ar] = bv.w;
        __syncthreads();
        #pragma unroll
        for (int kk = 0; kk < 16; kk++) {
            ulonglong2 bq  = *(const ulonglong2*)&Bs[kk][tx*4];
            ulonglong2 a01 = *(const ulonglong2*)&As2[kk][ty*8];
            ulonglong2 a23 = *(const ulonglong2*)&As2[kk][ty*8+4];
            acc[0][0]=fma2(a01.x,bq.x,acc[0][0]); acc[0][1]=fma2(a01.x,bq.y,acc[0][1]);
            acc[1][0]=fma2(a01.y,bq.x,acc[1][0]); acc[1][1]=fma2(a01.y,bq.y,acc[1][1]);
            acc[2][0]=fma2(a23.x,bq.x,acc[2][0]); acc[2][1]=fma2(a23.x,bq.y,acc[2][1]);
            acc[3][0]=fma2(a23.y,bq.x,acc[3][0]); acc[3][1]=fma2(a23.y,bq.y,acc[3][1]);
        }
        __syncthreads();
    }

    #pragma unroll
    for (int r = 0; r < 4; r++) {
        const int gr = row0 + ty*4 + r;
        if (gr >= C_CLS) continue;
        float c[4];
        upk2(acc[r][0], c[0], c[1]);
        upk2(acc[r][1], c[2], c[3]);
        #pragma unroll
        for (int j = 0; j < 4; j++) {
            const int gc = col0 + tx*4 + j;
            if (gc >= C_CLS) continue;
            float s = c[j];
            out[(size_t)gr * C_CLS + gc] = (s > THRESH) ? s * TEMP : -1e30f;
        }
    }
}

// ---------------- row softmax (in place, values pre-masked+scaled) ------
__global__ void softmax_kernel(float* __restrict__ attn)
{
    __shared__ float s_red[8];
    const int t = threadIdx.x, lane = t & 31, warp = t >> 5;
    float* row = attn + (size_t)blockIdx.x * C_CLS;

    float v[4];
    float m = -1e30f;
    #pragma unroll
    for (int i = 0; i < 4; i++) {
        int c = t + i * 256;
        v[i] = (c < C_CLS) ? row[c] : -1e30f;
        m = fmaxf(m, v[i]);
    }
    #pragma unroll
    for (int o = 16; o; o >>= 1) m = fmaxf(m, __shfl_xor_sync(0xffffffffu, m, o));
    if (lane == 0) s_red[warp] = m;
    __syncthreads();
    m = s_red[0];
    #pragma unroll
    for (int w = 1; w < 8; w++) m = fmaxf(m, s_red[w]);
    __syncthreads();

    float sum = 0.f;
    #pragma unroll
    for (int i = 0; i < 4; i++) {
        float e = (v[i] > -1e29f) ? __expf(v[i] - m) : 0.f;
        v[i] = e;
        sum += e;
    }
    #pragma unroll
    for (int o = 16; o; o >>= 1) sum += __shfl_xor_sync(0xffffffffu, sum, o);
    if (lane == 0) s_red[warp] = sum;
    __syncthreads();
    float tot = 0.f;
    #pragma unroll
    for (int w = 0; w < 8; w++) tot += s_red[w];
    float inv = 1.f / tot;
    #pragma unroll
    for (int i = 0; i < 4; i++) {
        int c = t + i * 256;
        if (c < C_CLS) row[c] = v[i] * inv;
    }
}

// ---------------- relation MLP: out[b,c] = fc_b + sum_h relu(a+p)*w -----
__global__ void relation_kernel(const float* __restrict__ img_h,
                                const float* __restrict__ proto_h,
                                const float* __restrict__ fc_w,
                                const float* __restrict__ fc_b,
                                float* __restrict__ out)
{
    __shared__ __align__(16) float s_a2[64][136];  // [h][2*b] duplicated
    __shared__ __align__(16) float s_p[64][68];    // [h][c]
    __shared__ __align__(16) float s_w2[2 * HH];   // duplicated weights
    const int tid = threadIdx.x;
    const int b0 = blockIdx.y * 64;
    const int c0 = blockIdx.x * 64;
    const int tx = tid & 15;        // c: tx*4
    const int ty = tid >> 4;        // b: ty*4
    const int bl = tid >> 2;        // loader row (0..63)
    const int hq = tid & 3;         // loader h-quad group

    if (tid < HH) { float w = fc_w[tid]; s_w2[2*tid] = w; s_w2[2*tid+1] = w; }

    ull acc[4][2];
    #pragma unroll
    for (int i = 0; i < 4; i++) { acc[i][0] = 0ull; acc[i][1] = 0ull; }

    const float* arow = img_h   + (size_t)(b0 + bl) * HH;
    const float* prow = proto_h + (size_t)min(c0 + bl, C_CLS - 1) * HH;

    for (int h0 = 0; h0 < HH; h0 += 64) {
        #pragma unroll
        for (int it = 0; it < 4; it++) {
            const int hh = (hq + 4*it) * 4;
            float4 va = *(const float4*)(arow + h0 + hh);
            float4 vp = *(const float4*)(prow + h0 + hh);
            *(float2*)&s_a2[hh+0][2*bl] = make_float2(va.x, va.x);
            *(float2*)&s_a2[hh+1][2*bl] = make_float2(va.y, va.y);
            *(float2*)&s_a2[hh+2][2*bl] = make_float2(va.z, va.z);
            *(float2*)&s_a2[hh+3][2*bl] = make_float2(va.w, va.w);
            s_p[hh+0][bl] = vp.x; s_p[hh+1][bl] = vp.y;
            s_p[hh+2][bl] = vp.z; s_p[hh+3][bl] = vp.w;
        }
        __syncthreads();
        #pragma unroll 4
        for (int hh = 0; hh < 64; hh++) {
            ull w2 = *(const ull*)&s_w2[2*(h0 + hh)];
            ulonglong2 aA = *(const ulonglong2*)&s_a2[hh][ty*8];
            ulonglong2 aB = *(const ulonglong2*)&s_a2[hh][ty*8+4];
            ulonglong2 pv = *(const ulonglong2*)&s_p[hh][tx*4];
            ull av[4] = {aA.x, aA.y, aB.x, aB.y};
            #pragma unroll
            for (int i = 0; i < 4; i++) {
                acc[i][0] = fma2(relu2(add2(av[i], pv.x)), w2, acc[i][0]);
                acc[i][1] = fma2(relu2(add2(av[i], pv.y)), w2, acc[i][1]);
            }
        }
        __syncthreads();
    }

    const float bias = fc_b[0];
    #pragma unroll
    for (int i = 0; i < 4; i++) {
        const int b = b0 + ty*4 + i;
        float c[4];
        upk2(acc[i][0], c[0], c[1]);
        upk2(acc[i][1], c[2], c[3]);
        const int cc = c0 + tx*4;
        if (cc + 3 < C_CLS) {
            float4 v = make_float4(c[0] + bias, c[1] + bias, c[2] + bias, c[3] + bias);
            *(float4*)&out[(size_t)b * C_CLS + cc] = v;
        } else {
            #pragma unroll
            for (int j = 0; j < 4; j++)
                if (cc + j < C_CLS) out[(size_t)b * C_CLS + cc + j] = c[j] + bias;
        }
    }
}

// ---------------- host launch ----------------
extern "C" void kernel_launch(void* const* d_in, const int* in_sizes, int n_in,
                              void* d_out, int out_size) {
    const float* image_feats = (const float*)d_in[0];  // [2048,2048]
    const float* img_proto   = (const float*)d_in[1];  // [1000,2048]
    const float* attributes  = (const float*)d_in[2];  // [1000,312]
    const float* att_g   = (const float*)d_in[4];      // [312,128]
    const float* slim_w  = (const float*)d_in[5];      // [2048,312]
    const float* slim_b  = (const float*)d_in[6];      // [312]
    const float* img_w   = (const float*)d_in[7];      // [2048,128]
    const float* proto_w = (const float*)d_in[8];      // [624,128]
    const float* proto_b = (const float*)d_in[9];      // [1,128]
    const float* fc_w    = (const float*)d_in[10];     // [128,1]
    const float* fc_b    = (const float*)d_in[11];     // [1]
    float* out = (float*)d_out;

    float *proto_red, *gnp, *attnp, *Mp, *proto_hp, *img_hp, *scrA, *scrB, *scrM;
    cudaGetSymbolAddress((void**)&proto_red, g_proto_red);
    cudaGetSymbolAddress((void**)&gnp,       g_gn);
    cudaGetSymbolAddress((void**)&attnp,     g_attn);
    cudaGetSymbolAddress((void**)&Mp,        g_M);
    cudaGetSymbolAddress((void**)&proto_hp,  g_proto_h);
    cudaGetSymbolAddress((void**)&img_hp,    g_img_h);
    cudaGetSymbolAddress((void**)&scrA,      g_scr_a);
    cudaGetSymbolAddress((void**)&scrB,      g_scr_b);
    cudaGetSymbolAddress((void**)&scrM,      g_scr_m);

    static cudaStream_t s1 = nullptr, s2 = nullptr, s3 = nullptr;
    static cudaEvent_t ev0 = nullptr, ev1 = nullptr, ev2 = nullptr, ev3 = nullptr;
    if (!s1) {
        cudaStreamCreateWithFlags(&s1, cudaStreamNonBlocking);
        cudaStreamCreateWithFlags(&s2, cudaStreamNonBlocking);
        cudaStreamCreateWithFlags(&s3, cudaStreamNonBlocking);
        cudaEventCreateWithFlags(&ev0, cudaEventDisableTiming);
        cudaEventCreateWithFlags(&ev1, cudaEventDisableTiming);
        cudaEventCreateWithFlags(&ev2, cudaEventDisableTiming);
        cudaEventCreateWithFlags(&ev3, cudaEventDisableTiming);
    }
    cudaStream_t s0 = 0;

    // fork
    cudaEventRecord(ev0, s0);
    cudaStreamWaitEvent(s1, ev0, 0);
    cudaStreamWaitEvent(s2, ev0, 0);
    cudaStreamWaitEvent(s3, ev0, 0);

    // ---- chain C (s1): gn -> sim -> softmax --------------------------------
    gn_kernel<<<C_CLS / 8, 128, 0, s1>>>(attributes, att_g, gnp);
    sim_kernel<<<dim3(16, 16), 256, 0, s1>>>(gnp, attnp);
    softmax_kernel<<<C_CLS, 256, 0, s1>>>(attnp);
    cudaEventRecord(ev1, s1);

    // ---- chain A (s2): img_h (split-K 16) ----------------------------------
    gemm256<<<dim3(1, 16, 16), 256, 0, s2>>>(image_feats, img_w, scrB,
                                             BB, HH, DIMG, 128);
    reduce_k<<<(BB*HH/4 + 255)/256, 256, 0, s2>>>(img_hp, scrB, BB*HH/4, 16, nullptr, HH);
    cudaEventRecord(ev2, s2);

    // ---- chain D (s3): M_top = attributes @ proto_w[0:312] (slices 0..3) ---
    gemm256<<<dim3(1, 8, 4), 256, 0, s3>>>(attributes, proto_w, scrM,
                                           C_CLS, HH, DATT, 80);
    cudaEventRecord(ev3, s3);

    // ---- chain B (s0): proto_red -> M_bot -> M -> proto_h -> relation ------
    gemm256<<<dim3(3, 8, 16), 256, 0, s0>>>(img_proto, slim_w, scrA,
                                            C_CLS, DATT, DIMG, 128);
    reduce_k<<<(C_CLS*DATT/4 + 255)/256, 256, 0, s0>>>(proto_red, scrA, C_CLS*DATT/4, 16, slim_b, DATT);
    // M_bot partials into slices 4..7
    gemm256<<<dim3(1, 8, 4), 256, 0, s0>>>(proto_red, proto_w + (size_t)DATT * HH,
                                           scrM + 4 * (size_t)C_CLS * HH,
                                           C_CLS, HH, DATT, 80);
    // M = sum(8 slices) + proto_b
    cudaStreamWaitEvent(s0, ev3, 0);
    reduce_k<<<(C_CLS*HH/4 + 255)/256, 256, 0, s0>>>(Mp, scrM, C_CLS*HH/4, 8, proto_b, HH);

    // proto_h = attn @ M (split-K 32; proto_b folded via softmax row-sum = 1)
    cudaStreamWaitEvent(s0, ev1, 0);
    gemm256<<<dim3(1, 8, 32), 256, 0, s0>>>(attnp, Mp, scrA, C_CLS, HH, C_CLS, 32);
    reduce_k<<<(C_CLS*HH/4 + 255)/256, 256, 0, s0>>>(proto_hp, scrA, C_CLS*HH/4, 32, nullptr, HH);

    // ---- join: relation ----------------------------------------------------
    cudaStreamWaitEvent(s0, ev2, 0);
    relation_kernel<<<dim3(16, 32), 256, 0, s0>>>(img_hp, proto_hp, fc_w, fc_b, out);
}

// round 10
// speedup vs baseline: 1.1178x; 1.0246x over previous
#include <cuda_runtime.h>
#include <math.h>

// ---------------- problem constants ----------------
#define C_CLS   1000
#define DIMG    2048
#define DATT    312
#define HH      128
#define BB      2048
#define THRESH  0.76604444311897803f   // cos(40 deg)
#define TEMP    32.0f

typedef unsigned long long ull;

// ---------------- scratch (device globals; no allocation allowed) -------
__device__ float g_gn[C_CLS * HH];                 // [1000,128]
__device__ float g_attn[C_CLS * C_CLS];            // [1000,1000]
__device__ float g_M[C_CLS * HH];                  // [1000,128]
__device__ float g_proto_h[C_CLS * HH];            // [1000,128]
__device__ float g_img_h[BB * HH];                 // [2048,128]
__device__ float g_W2[DIMG * HH];                  // slim_w @ proto_w_bot [2048,128]
__device__ float g_b2[HH];                         // slim_b@proto_w_bot + proto_b
__device__ float g_scr_a[32 * C_CLS * HH + 4 * DIMG * HH]; // proto_h + W2 partials
__device__ float g_scr_b[16 * BB * HH];            // img_h partials
__device__ float g_scr_m[16 * C_CLS * HH];         // M partials (4 top + 12 bot)

// ---------------- packed f32x2 helpers ----------------
__device__ __forceinline__ ull pk2(float x, float y) {
    ull r;
    asm("mov.b64 %0, {%1, %2};" : "=l"(r) : "r"(__float_as_uint(x)), "r"(__float_as_uint(y)));
    return r;
}
__device__ __forceinline__ ull fma2(ull a, ull b, ull c) {
    ull d;
    asm("fma.rn.f32x2 %0, %1, %2, %3;" : "=l"(d) : "l"(a), "l"(b), "l"(c));
    return d;
}
__device__ __forceinline__ ull add2(ull a, ull b) {
    ull d;
    asm("add.rn.f32x2 %0, %1, %2;" : "=l"(d) : "l"(a), "l"(b));
    return d;
}
__device__ __forceinline__ void upk2(ull v, float& x, float& y) {
    unsigned lo, hi;
    asm("mov.b64 {%0, %1}, %2;" : "=r"(lo), "=r"(hi) : "l"(v));
    x = __uint_as_float(lo); y = __uint_as_float(hi);
}
__device__ __forceinline__ ull relu2(ull v) {
    float a, b;
    upk2(v, a, b);
    return pk2(fmaxf(a, 0.f), fmaxf(b, 0.f));
}

// ---------------- big GEMM: C = A[MxK] @ B[KxN], BM=128 BN=128 BK=16 ----
// 256 threads, 8x8/thread, FFMA2 inner loop, ping-pong smem, split-K.
__global__ void __launch_bounds__(256)
gemm256(const float* __restrict__ A, const float* __restrict__ B,
        float* __restrict__ Cpart, int M, int N, int K, int Ks)
{
    __shared__ __align__(16) float As[2][16][132];
    __shared__ __align__(16) float Bs[2][16][132];
    const int tid = threadIdx.x;
    const int z = blockIdx.z;
    const int kbeg = z * Ks;                        // Ks multiple of 4
    const int kend = min(K, kbeg + Ks);
    const int row0 = blockIdx.y * 128;
    const int col0 = blockIdx.x * 128;
    const int tx = tid & 15;        // cols: tx*8
    const int ty = tid >> 4;        // rows: ty*8
    const int akq = tid & 3;        // A loader k-quad
    const int ar  = tid >> 2;       // A loader row (0..63, +64 second)
    const int br  = tid >> 4;       // B loader k-row (0..15)
    const int bcq = tid & 15;       // B loader col-octet

    ull acc[8][4];
    #pragma unroll
    for (int r = 0; r < 8; r++)
        #pragma unroll
        for (int j = 0; j < 4; j++) acc[r][j] = 0ull;

    const int arow0 = min(row0 + ar,      M - 1);
    const int arow1 = min(row0 + ar + 64, M - 1);
    const float* Ar0 = A + (size_t)arow0 * K;
    const float* Ar1 = A + (size_t)arow1 * K;
    const bool colFast = (col0 + 127 < N);

    float4 sa0, sa1, sb0, sb1;   // staging registers

    auto loadTile = [&](int kb) {
        const int ka = kb + akq * 4;
        if (ka + 3 < kend) {
            sa0 = *(const float4*)(Ar0 + ka);
            sa1 = *(const float4*)(Ar1 + ka);
        } else {
            sa0.x = (ka+0 < kend) ? Ar0[ka+0] : 0.f;
            sa0.y = (ka+1 < kend) ? Ar0[ka+1] : 0.f;
            sa0.z = (ka+2 < kend) ? Ar0[ka+2] : 0.f;
            sa0.w = (ka+3 < kend) ? Ar0[ka+3] : 0.f;
            sa1.x = (ka+0 < kend) ? Ar1[ka+0] : 0.f;
            sa1.y = (ka+1 < kend) ? Ar1[ka+1] : 0.f;
            sa1.z = (ka+2 < kend) ? Ar1[ka+2] : 0.f;
            sa1.w = (ka+3 < kend) ? Ar1[ka+3] : 0.f;
        }
        const int kb2 = kb + br;
        const int bc = col0 + bcq * 8;
        sb0 = make_float4(0.f, 0.f, 0.f, 0.f);
        sb1 = sb0;
        if (kb2 < kend) {
            const float* Bp = B + (size_t)kb2 * N;
            if (colFast) {
                sb0 = *(const float4*)(Bp + bc);
                sb1 = *(const float4*)(Bp + bc + 4);
            } else {
                if (bc+0 < N) sb0.x = Bp[bc+0];
                if (bc+1 < N) sb0.y = Bp[bc+1];
                if (bc+2 < N) sb0.z = Bp[bc+2];
                if (bc+3 < N) sb0.w = Bp[bc+3];
                if (bc+4 < N) sb1.x = Bp[bc+4];
                if (bc+5 < N) sb1.y = Bp[bc+5];
                if (bc+6 < N) sb1.z = Bp[bc+6];
                if (bc+7 < N) sb1.w = Bp[bc+7];
            }
        }
    };
    auto storeTile = [&](int p) {
        As[p][akq*4+0][ar]    = sa0.x;
        As[p][akq*4+1][ar]    = sa0.y;
        As[p][akq*4+2][ar]    = sa0.z;
        As[p][akq*4+3][ar]    = sa0.w;
        As[p][akq*4+0][ar+64] = sa1.x;
        As[p][akq*4+1][ar+64] = sa1.y;
        As[p][akq*4+2][ar+64] = sa1.z;
        As[p][akq*4+3][ar+64] = sa1.w;
        *(float4*)&Bs[p][br][bcq*8]     = sb0;
        *(float4*)&Bs[p][br][bcq*8 + 4] = sb1;
    };

    loadTile(kbeg);
    storeTile(0);
    __syncthreads();

    int p = 0;
    for (int k0 = kbeg; k0 < kend; k0 += 16) {
        const bool hasNext = (k0 + 16) < kend;
        if (hasNext) loadTile(k0 + 16);       // LDG overlapped with compute

        #pragma unroll
        for (int kk = 0; kk < 16; kk++) {
            float4 af0 = *(const float4*)&As[p][kk][ty*8];
            float4 af1 = *(const float4*)&As[p][kk][ty*8 + 4];
            ulonglong2 b01 = *(const ulonglong2*)&Bs[p][kk][tx*8];
            ulonglong2 b23 = *(const ulonglong2*)&Bs[p][kk][tx*8 + 4];
            ull ad;
            ad = pk2(af0.x, af0.x);
            acc[0][0]=fma2(ad,b01.x,acc[0][0]); acc[0][1]=fma2(ad,b01.y,acc[0][1]);
            acc[0][2]=fma2(ad,b23.x,acc[0][2]); acc[0][3]=fma2(ad,b23.y,acc[0][3]);
            ad = pk2(af0.y, af0.y);
            acc[1][0]=fma2(ad,b01.x,acc[1][0]); acc[1][1]=fma2(ad,b01.y,acc[1][1]);
            acc[1][2]=fma2(ad,b23.x,acc[1][2]); acc[1][3]=fma2(ad,b23.y,acc[1][3]);
            ad = pk2(af0.z, af0.z);
            acc[2][0]=fma2(ad,b01.x,acc[2][0]); acc[2][1]=fma2(ad,b01.y,acc[2][1]);
            acc[2][2]=fma2(ad,b23.x,acc[2][2]); acc[2][3]=fma2(ad,b23.y,acc[2][3]);
            ad = pk2(af0.w, af0.w);
            acc[3][0]=fma2(ad,b01.x,acc[3][0]); acc[3][1]=fma2(ad,b01.y,acc[3][1]);
            acc[3][2]=fma2(ad,b23.x,acc[3][2]); acc[3][3]=fma2(ad,b23.y,acc[3][3]);
            ad = pk2(af1.x, af1.x);
            acc[4][0]=fma2(ad,b01.x,acc[4][0]); acc[4][1]=fma2(ad,b01.y,acc[4][1]);
            acc[4][2]=fma2(ad,b23.x,acc[4][2]); acc[4][3]=fma2(ad,b23.y,acc[4][3]);
            ad = pk2(af1.y, af1.y);
            acc[5][0]=fma2(ad,b01.x,acc[5][0]); acc[5][1]=fma2(ad,b01.y,acc[5][1]);
            acc[5][2]=fma2(ad,b23.x,acc[5][2]); acc[5][3]=fma2(ad,b23.y,acc[5][3]);
            ad = pk2(af1.z, af1.z);
            acc[6][0]=fma2(ad,b01.x,acc[6][0]); acc[6][1]=fma2(ad,b01.y,acc[6][1]);
            acc[6][2]=fma2(ad,b23.x,acc[6][2]); acc[6][3]=fma2(ad,b23.y,acc[6][3]);
            ad = pk2(af1.w, af1.w);
            acc[7][0]=fma2(ad,b01.x,acc[7][0]); acc[7][1]=fma2(ad,b01.y,acc[7][1]);
            acc[7][2]=fma2(ad,b23.x,acc[7][2]); acc[7][3]=fma2(ad,b23.y,acc[7][3]);
        }
        if (hasNext) {
            storeTile(p ^ 1);                 // write OTHER buffer: no race
            __syncthreads();                  // one barrier per tile
            p ^= 1;
        }
    }

    float* Co = Cpart + (size_t)z * M * N;
    #pragma unroll
    for (int r = 0; r < 8; r++) {
        const int gr = row0 + ty*8 + r;
        if (gr >= M) continue;
        float c[8];
        upk2(acc[r][0], c[0], c[1]);
        upk2(acc[r][1], c[2], c[3]);
        upk2(acc[r][2], c[4], c[5]);
        upk2(acc[r][3], c[6], c[7]);
        const int gc = col0 + tx*8;
        if (gc + 7 < N) {
            *(float4*)&Co[(size_t)gr * N + gc]     = make_float4(c[0], c[1], c[2], c[3]);
            *(float4*)&Co[(size_t)gr * N + gc + 4] = make_float4(c[4], c[5], c[6], c[7]);
        } else {
            #pragma unroll
            for (int j = 0; j < 8; j++)
                if (gc + j < N) Co[(size_t)gr * N + gc + j] = c[j];
        }
    }
}

// ---------------- reduce split-K partials (+optional bias), any S -------
__global__ void reduce_k(float* __restrict__ out, const float* __restrict__ part,
                         int lenf4, int S, const float* __restrict__ bias, int N)
{
    int i = blockIdx.x * blockDim.x + threadIdx.x;
    if (i >= lenf4) return;
    const float4* p = (const float4*)part;
    float4 a0 = make_float4(0.f,0.f,0.f,0.f), a1 = a0, a2 = a0, a3 = a0;
    int z = 0;
    for (; z + 4 <= S; z += 4) {
        float4 t0 = p[(size_t)(z+0) * lenf4 + i];
        float4 t1 = p[(size_t)(z+1) * lenf4 + i];
        float4 t2 = p[(size_t)(z+2) * lenf4 + i];
        float4 t3 = p[(size_t)(z+3) * lenf4 + i];
        a0.x += t0.x; a0.y += t0.y; a0.z += t0.z; a0.w += t0.w;
        a1.x += t1.x; a1.y += t1.y; a1.z += t1.z; a1.w += t1.w;
        a2.x += t2.x; a2.y += t2.y; a2.z += t2.z; a2.w += t2.w;
        a3.x += t3.x; a3.y += t3.y; a3.z += t3.z; a3.w += t3.w;
    }
    for (; z < S; z++) {
        float4 t = p[(size_t)z * lenf4 + i];
        a0.x += t.x; a0.y += t.y; a0.z += t.z; a0.w += t.w;
    }
    float4 acc = make_float4(a0.x + a1.x + a2.x + a3.x,
                             a0.y + a1.y + a2.y + a3.y,
                             a0.z + a1.z + a2.z + a3.z,
                             a0.w + a1.w + a2.w + a3.w);
    if (bias) {
        int col = (i * 4) % N;      // N % 4 == 0 for all uses
        acc.x += bias[col+0]; acc.y += bias[col+1];
        acc.z += bias[col+2]; acc.w += bias[col+3];
    }
    ((float4*)out)[i] = acc;
}

// ---------------- b2 = slim_b @ proto_w_bot + proto_b  [128] ------------
__global__ void b2_kernel(const float* __restrict__ slim_b,
                          const float* __restrict__ proto_w_bot,
                          const float* __restrict__ proto_b,
                          float* __restrict__ b2)
{
    const int j = threadIdx.x;     // 128
    float acc = 0.f;
    for (int k = 0; k < DATT; k++)
        acc = fmaf(slim_b[k], proto_w_bot[(size_t)k * HH + j], acc);
    b2[j] = acc + proto_b[j];
}

// ---------------- gn = normalize_rows(attributes @ att_g) ----------------
__global__ void gn_kernel(const float* __restrict__ attrs,
                          const float* __restrict__ att_g,
                          float* __restrict__ gn) {
    __shared__ float s_attr[8][DATT];
    __shared__ float s_red[8][4];
    const int c0 = blockIdx.x * 8;
    const int t = threadIdx.x;       // 128
    const int lane = t & 31, warp = t >> 5;

    for (int i = t; i < 8 * DATT; i += 128) {
        int r = i / DATT, k = i - r * DATT;
        s_attr[r][k] = attrs[(size_t)(c0 + r) * DATT + k];
    }
    __syncthreads();

    float acc[8] = {0.f,0.f,0.f,0.f,0.f,0.f,0.f,0.f};
    for (int k = 0; k < DATT; k++) {
        float w = att_g[(size_t)k * HH + t];
        #pragma unroll
        for (int r = 0; r < 8; r++) acc[r] = fmaf(s_attr[r][k], w, acc[r]);
    }
    #pragma unroll
    for (int r = 0; r < 8; r++) {
        float sq = acc[r] * acc[r];
        #pragma unroll
        for (int o = 16; o; o >>= 1) sq += __shfl_xor_sync(0xffffffffu, sq, o);
        if (lane == 0) s_red[r][warp] = sq;
    }
    __syncthreads();
    #pragma unroll
    for (int r = 0; r < 8; r++) {
        float tot = s_red[r][0] + s_red[r][1] + s_red[r][2] + s_red[r][3];
        float inv = 1.f / fmaxf(sqrtf(tot), 1e-12f);
        gn[(size_t)(c0 + r) * HH + t] = acc[r] * inv;
    }
}

// ---------------- sim = gn @ gn^T, masked+scaled in epilogue ------------
__global__ void sim_kernel(const float* __restrict__ gn, float* __restrict__ out)
{
    __shared__ __align__(16) float As2[16][140];
    __shared__ __align__(16) float Bs[16][68];
    const int tid = threadIdx.x;
    const int row0 = blockIdx.y * 64;
    const int col0 = blockIdx.x * 64;
    const int tx = tid & 15, ty = tid >> 4;
    const int ar = tid >> 2, akq = tid & 3;

    const float* Arp = gn + (size_t)min(row0 + ar, C_CLS - 1) * HH;
    const float* Brp = gn + (size_t)min(col0 + ar, C_CLS - 1) * HH;

    ull acc[4][2];
    #pragma unroll
    for (int r = 0; r < 4; r++) { acc[r][0] = 0ull; acc[r][1] = 0ull; }

    for (int k0 = 0; k0 < HH; k0 += 16) {
        float4 av = *(const float4*)(Arp + k0 + akq*4);
        float4 bv = *(const float4*)(Brp + k0 + akq*4);
        *(float2*)&As2[akq*4+0][2*ar] = make_float2(av.x, av.x);
        *(float2*)&As2[akq*4+1][2*ar] = make_float2(av.y, av.y);
        *(float2*)&As2[akq*4+2][2*ar] = make_float2(av.z, av.z);
        *(float2*)&As2[akq*4+3][2*ar] = make_float2(av.w, av.w);
        Bs[akq*4+0][ar] = bv.x; Bs[akq*4+1][ar] = bv.y;
        Bs[akq*4+2][ar] = bv.z; Bs[akq*4+3][ar] = bv.w;
        __syncthreads();
        #pragma unroll
        for (int kk = 0; kk < 16; kk++) {
            ulonglong2 bq  = *(const ulonglong2*)&Bs[kk][tx*4];
            ulonglong2 a01 = *(const ulonglong2*)&As2[kk][ty*8];
            ulonglong2 a23 = *(const ulonglong2*)&As2[kk][ty*8+4];
            acc[0][0]=fma2(a01.x,bq.x,acc[0][0]); acc[0][1]=fma2(a01.x,bq.y,acc[0][1]);
            acc[1][0]=fma2(a01.y,bq.x,acc[1][0]); acc[1][1]=fma2(a01.y,bq.y,acc[1][1]);
            acc[2][0]=fma2(a23.x,bq.x,acc[2][0]); acc[2][1]=fma2(a23.x,bq.y,acc[2][1]);
            acc[3][0]=fma2(a23.y,bq.x,acc[3][0]); acc[3][1]=fma2(a23.y,bq.y,acc[3][1]);
        }
        __syncthreads();
    }

    #pragma unroll
    for (int r = 0; r < 4; r++) {
        const int gr = row0 + ty*4 + r;
        if (gr >= C_CLS) continue;
        float c[4];
        upk2(acc[r][0], c[0], c[1]);
        upk2(acc[r][1], c[2], c[3]);
        #pragma unroll
        for (int j = 0; j < 4; j++) {
            const int gc = col0 + tx*4 + j;
            if (gc >= C_CLS) continue;
            float s = c[j];
            out[(size_t)gr * C_CLS + gc] = (s > THRESH) ? s * TEMP : -1e30f;
        }
    }
}

// ---------------- row softmax (in place, values pre-masked+scaled) ------
__global__ void softmax_kernel(float* __restrict__ attn)
{
    __shared__ float s_red[8];
    const int t = threadIdx.x, lane = t & 31, warp = t >> 5;
    float* row = attn + (size_t)blockIdx.x * C_CLS;

    float v[4];
    float m = -1e30f;
    #pragma unroll
    for (int i = 0; i < 4; i++) {
        int c = t + i * 256;
        v[i] = (c < C_CLS) ? row[c] : -1e30f;
        m = fmaxf(m, v[i]);
    }
    #pragma unroll
    for (int o = 16; o; o >>= 1) m = fmaxf(m, __shfl_xor_sync(0xffffffffu, m, o));
    if (lane == 0) s_red[warp] = m;
    __syncthreads();
    m = s_red[0];
    #pragma unroll
    for (int w = 1; w < 8; w++) m = fmaxf(m, s_red[w]);
    __syncthreads();

    float sum = 0.f;
    #pragma unroll
    for (int i = 0; i < 4; i++) {
        float e = (v[i] > -1e29f) ? __expf(v[i] - m) : 0.f;
        v[i] = e;
        sum += e;
    }
    #pragma unroll
    for (int o = 16; o; o >>= 1) sum += __shfl_xor_sync(0xffffffffu, sum, o);
    if (lane == 0) s_red[warp] = sum;
    __syncthreads();
    float tot = 0.f;
    #pragma unroll
    for (int w = 0; w < 8; w++) tot += s_red[w];
    float inv = 1.f / tot;
    #pragma unroll
    for (int i = 0; i < 4; i++) {
        int c = t + i * 256;
        if (c < C_CLS) row[c] = v[i] * inv;
    }
}

// ---------------- relation MLP: out[b,c] = fc_b + sum_h relu(a+p)*w -----
__global__ void relation_kernel(const float* __restrict__ img_h,
                                const float* __restrict__ proto_h,
                                const float* __restrict__ fc_w,
                                const float* __restrict__ fc_b,
                                float* __restrict__ out)
{
    __shared__ __align__(16) float s_a2[64][136];  // [h][2*b] duplicated
    __shared__ __align__(16) float s_p[64][68];    // [h][c]
    __shared__ __align__(16) float s_w2[2 * HH];   // duplicated weights
    const int tid = threadIdx.x;
    const int b0 = blockIdx.y * 64;
    const int c0 = blockIdx.x * 64;
    const int tx = tid & 15;        // c: tx*4
    const int ty = tid >> 4;        // b: ty*4
    const int bl = tid >> 2;        // loader row (0..63)
    const int hq = tid & 3;         // loader h-quad group

    if (tid < HH) { float w = fc_w[tid]; s_w2[2*tid] = w; s_w2[2*tid+1] = w; }

    ull acc[4][2];
    #pragma unroll
    for (int i = 0; i < 4; i++) { acc[i][0] = 0ull; acc[i][1] = 0ull; }

    const float* arow = img_h   + (size_t)(b0 + bl) * HH;
    const float* prow = proto_h + (size_t)min(c0 + bl, C_CLS - 1) * HH;

    for (int h0 = 0; h0 < HH; h0 += 64) {
        #pragma unroll
        for (int it = 0; it < 4; it++) {
            const int hh = (hq + 4*it) * 4;
            float4 va = *(const float4*)(arow + h0 + hh);
            float4 vp = *(const float4*)(prow + h0 + hh);
            *(float2*)&s_a2[hh+0][2*bl] = make_float2(va.x, va.x);
            *(float2*)&s_a2[hh+1][2*bl] = make_float2(va.y, va.y);
            *(float2*)&s_a2[hh+2][2*bl] = make_float2(va.z, va.z);
            *(float2*)&s_a2[hh+3][2*bl] = make_float2(va.w, va.w);
            s_p[hh+0][bl] = vp.x; s_p[hh+1][bl] = vp.y;
            s_p[hh+2][bl] = vp.z; s_p[hh+3][bl] = vp.w;
        }
        __syncthreads();
        #pragma unroll 4
        for (int hh = 0; hh < 64; hh++) {
            ull w2 = *(const ull*)&s_w2[2*(h0 + hh)];
            ulonglong2 aA = *(const ulonglong2*)&s_a2[hh][ty*8];
            ulonglong2 aB = *(const ulonglong2*)&s_a2[hh][ty*8+4];
            ulonglong2 pv = *(const ulonglong2*)&s_p[hh][tx*4];
            ull av[4] = {aA.x, aA.y, aB.x, aB.y};
            #pragma unroll
            for (int i = 0; i < 4; i++) {
                acc[i][0] = fma2(relu2(add2(av[i], pv.x)), w2, acc[i][0]);
                acc[i][1] = fma2(relu2(add2(av[i], pv.y)), w2, acc[i][1]);
            }
        }
        __syncthreads();
    }

    const float bias = fc_b[0];
    #pragma unroll
    for (int i = 0; i < 4; i++) {
        const int b = b0 + ty*4 + i;
        float c[4];
        upk2(acc[i][0], c[0], c[1]);
        upk2(acc[i][1], c[2], c[3]);
        const int cc = c0 + tx*4;
        if (cc + 3 < C_CLS) {
            float4 v = make_float4(c[0] + bias, c[1] + bias, c[2] + bias, c[3] + bias);
            *(float4*)&out[(size_t)b * C_CLS + cc] = v;
        } else {
            #pragma unroll
            for (int j = 0; j < 4; j++)
                if (cc + j < C_CLS) out[(size_t)b * C_CLS + cc + j] = c[j] + bias;
        }
    }
}

// ---------------- host launch ----------------
extern "C" void kernel_launch(void* const* d_in, const int* in_sizes, int n_in,
                              void* d_out, int out_size) {
    const float* image_feats = (const float*)d_in[0];  // [2048,2048]
    const float* img_proto   = (const float*)d_in[1];  // [1000,2048]
    const float* attributes  = (const float*)d_in[2];  // [1000,312]
    const float* att_g   = (const float*)d_in[4];      // [312,128]
    const float* slim_w  = (const float*)d_in[5];      // [2048,312]
    const float* slim_b  = (const float*)d_in[6];      // [312]
    const float* img_w   = (const float*)d_in[7];      // [2048,128]
    const float* proto_w = (const float*)d_in[8];      // [624,128]
    const float* proto_b = (const float*)d_in[9];      // [1,128]
    const float* fc_w    = (const float*)d_in[10];     // [128,1]
    const float* fc_b    = (const float*)d_in[11];     // [1]
    float* out = (float*)d_out;
    const float* proto_w_bot = proto_w + (size_t)DATT * HH;

    float *gnp, *attnp, *Mp, *proto_hp, *img_hp, *W2p, *b2p, *scrA, *scrB, *scrM;
    cudaGetSymbolAddress((void**)&gnp,       g_gn);
    cudaGetSymbolAddress((void**)&attnp,     g_attn);
    cudaGetSymbolAddress((void**)&Mp,        g_M);
    cudaGetSymbolAddress((void**)&proto_hp,  g_proto_h);
    cudaGetSymbolAddress((void**)&img_hp,    g_img_h);
    cudaGetSymbolAddress((void**)&W2p,       g_W2);
    cudaGetSymbolAddress((void**)&b2p,       g_b2);
    cudaGetSymbolAddress((void**)&scrA,      g_scr_a);
    cudaGetSymbolAddress((void**)&scrB,      g_scr_b);
    cudaGetSymbolAddress((void**)&scrM,      g_scr_m);
    float* scrW2 = scrA + (size_t)32 * C_CLS * HH;   // W2 partials (4 slices)

    static cudaStream_t s1 = nullptr, s2 = nullptr, s3 = nullptr;
    static cudaEvent_t ev0 = nullptr, ev1 = nullptr, ev2 = nullptr, ev3 = nullptr;
    if (!s1) {
        cudaStreamCreateWithFlags(&s1, cudaStreamNonBlocking);
        cudaStreamCreateWithFlags(&s2, cudaStreamNonBlocking);
        cudaStreamCreateWithFlags(&s3, cudaStreamNonBlocking);
        cudaEventCreateWithFlags(&ev0, cudaEventDisableTiming);
        cudaEventCreateWithFlags(&ev1, cudaEventDisableTiming);
        cudaEventCreateWithFlags(&ev2, cudaEventDisableTiming);
        cudaEventCreateWithFlags(&ev3, cudaEventDisableTiming);
    }
    cudaStream_t s0 = 0;

    // fork
    cudaEventRecord(ev0, s0);
    cudaStreamWaitEvent(s1, ev0, 0);
    cudaStreamWaitEvent(s2, ev0, 0);
    cudaStreamWaitEvent(s3, ev0, 0);

    // ---- chain C (s1): gn -> sim -> softmax --------------------------------
    gn_kernel<<<C_CLS / 8, 128, 0, s1>>>(attributes, att_g, gnp);
    sim_kernel<<<dim3(16, 16), 256, 0, s1>>>(gnp, attnp);
    softmax_kernel<<<C_CLS, 256, 0, s1>>>(attnp);
    cudaEventRecord(ev1, s1);

    // ---- chain A (s2): img_h (split-K 16) ----------------------------------
    gemm256<<<dim3(1, 16, 16), 256, 0, s2>>>(image_feats, img_w, scrB,
                                             BB, HH, DIMG, 128);
    reduce_k<<<(BB*HH/4 + 255)/256, 256, 0, s2>>>(img_hp, scrB, BB*HH/4, 16, nullptr, HH);
    cudaEventRecord(ev2, s2);

    // ---- chain D (s3): W2 = slim_w @ proto_w_bot [2048,128] + b2 vector ----
    gemm256<<<dim3(1, 16, 4), 256, 0, s3>>>(slim_w, proto_w_bot, scrW2,
                                            DIMG, HH, DATT, 80);
    reduce_k<<<(DIMG*HH/4 + 255)/256, 256, 0, s3>>>(W2p, scrW2, DIMG*HH/4, 4, nullptr, HH);
    b2_kernel<<<1, HH, 0, s3>>>(slim_b, proto_w_bot, proto_b, b2p);
    cudaEventRecord(ev3, s3);

    // ---- chain B (s0): M_top -> M_bot (via W2) -> M -> proto_h -> relation -
    // M_top = attributes @ proto_w_top, slices 0..3
    gemm256<<<dim3(1, 8, 4), 256, 0, s0>>>(attributes, proto_w, scrM,
                                           C_CLS, HH, DATT, 80);
    // M_bot = img_proto @ W2, slices 4..15 (12-way split-K over 2048)
    cudaStreamWaitEvent(s0, ev3, 0);
    gemm256<<<dim3(1, 8, 12), 256, 0, s0>>>(img_proto, W2p,
                                            scrM + 4 * (size_t)C_CLS * HH,
                                            C_CLS, HH, DIMG, 172);
    // M = sum(16 slices) + b2  (b2 = slim_b@proto_w_bot + proto_b)
    reduce_k<<<(C_CLS*HH/4 + 255)/256, 256, 0, s0>>>(Mp, scrM, C_CLS*HH/4, 16, b2p, HH);

    // proto_h = attn @ M (split-K 32; b2/proto_b folded via softmax row-sum=1)
    cudaStreamWaitEvent(s0, ev1, 0);
    gemm256<<<dim3(1, 8, 32), 256, 0, s0>>>(attnp, Mp, scrA, C_CLS, HH, C_CLS, 32);
    reduce_k<<<(C_CLS*HH/4 + 255)/256, 256, 0, s0>>>(proto_hp, scrA, C_CLS*HH/4, 32, nullptr, HH);

    // ---- join: relation ----------------------------------------------------
    cudaStreamWaitEvent(s0, ev2, 0);
    relation_kernel<<<dim3(16, 32), 256, 0, s0>>>(img_hp, proto_hp, fc_w, fc_b, out);
}

// round 11
// speedup vs baseline: 1.1907x; 1.0652x over previous
#include <cuda_runtime.h>
#include <math.h>

// ---------------- problem constants ----------------
#define C_CLS   1000
#define DIMG    2048
#define DATT    312
#define HH      128
#define BB      2048
#define THRESH  0.76604444311897803f   // cos(40 deg)
#define TEMP    32.0f

typedef unsigned long long ull;

// ---------------- scratch (device globals; no allocation allowed) -------
__device__ float g_gn[C_CLS * HH];                 // [1000,128]
__device__ float g_attn[C_CLS * C_CLS];            // [1000,1000]
__device__ float g_M[C_CLS * HH];                  // [1000,128]
__device__ float g_proto_h[C_CLS * HH];            // [1000,128]
__device__ float g_img_h[BB * HH];                 // [2048,128]
__device__ float g_W2[DIMG * HH];                  // slim_w @ proto_w_bot [2048,128]
__device__ float g_b2[HH];                         // slim_b@proto_w_bot + proto_b
__device__ float g_scr_a[32 * C_CLS * HH + 4 * DIMG * HH]; // proto_h + W2 partials
__device__ float g_scr_b[24 * BB * HH];            // img_h partials
__device__ float g_scr_m[28 * C_CLS * HH];         // M partials (4 top + 24 bot)

// ---------------- packed f32x2 helpers ----------------
__device__ __forceinline__ ull pk2(float x, float y) {
    ull r;
    asm("mov.b64 %0, {%1, %2};" : "=l"(r) : "r"(__float_as_uint(x)), "r"(__float_as_uint(y)));
    return r;
}
__device__ __forceinline__ ull fma2(ull a, ull b, ull c) {
    ull d;
    asm("fma.rn.f32x2 %0, %1, %2, %3;" : "=l"(d) : "l"(a), "l"(b), "l"(c));
    return d;
}
__device__ __forceinline__ ull add2(ull a, ull b) {
    ull d;
    asm("add.rn.f32x2 %0, %1, %2;" : "=l"(d) : "l"(a), "l"(b));
    return d;
}
__device__ __forceinline__ void upk2(ull v, float& x, float& y) {
    unsigned lo, hi;
    asm("mov.b64 {%0, %1}, %2;" : "=r"(lo), "=r"(hi) : "l"(v));
    x = __uint_as_float(lo); y = __uint_as_float(hi);
}
__device__ __forceinline__ ull relu2(ull v) {
    float a, b;
    upk2(v, a, b);
    return pk2(fmaxf(a, 0.f), fmaxf(b, 0.f));
}

// ---------------- big GEMM: C = A[MxK] @ B[KxN], BM=128 BN=128 BK=16 ----
// 256 threads, 8x8/thread, FFMA2 inner loop, ping-pong smem, split-K.
__global__ void __launch_bounds__(256)
gemm256(const float* __restrict__ A, const float* __restrict__ B,
        float* __restrict__ Cpart, int M, int N, int K, int Ks)
{
    __shared__ __align__(16) float As[2][16][132];
    __shared__ __align__(16) float Bs[2][16][132];
    const int tid = threadIdx.x;
    const int z = blockIdx.z;
    const int kbeg = z * Ks;                        // Ks multiple of 4
    const int kend = min(K, kbeg + Ks);
    const int row0 = blockIdx.y * 128;
    const int col0 = blockIdx.x * 128;
    const int tx = tid & 15;        // cols: tx*8
    const int ty = tid >> 4;        // rows: ty*8
    const int akq = tid & 3;        // A loader k-quad
    const int ar  = tid >> 2;       // A loader row (0..63, +64 second)
    const int br  = tid >> 4;       // B loader k-row (0..15)
    const int bcq = tid & 15;       // B loader col-octet

    ull acc[8][4];
    #pragma unroll
    for (int r = 0; r < 8; r++)
        #pragma unroll
        for (int j = 0; j < 4; j++) acc[r][j] = 0ull;

    const int arow0 = min(row0 + ar,      M - 1);
    const int arow1 = min(row0 + ar + 64, M - 1);
    const float* Ar0 = A + (size_t)arow0 * K;
    const float* Ar1 = A + (size_t)arow1 * K;
    const bool colFast = (col0 + 127 < N);

    float4 sa0, sa1, sb0, sb1;   // staging registers

    auto loadTile = [&](int kb) {
        const int ka = kb + akq * 4;
        if (ka + 3 < kend) {
            sa0 = *(const float4*)(Ar0 + ka);
            sa1 = *(const float4*)(Ar1 + ka);
        } else {
            sa0.x = (ka+0 < kend) ? Ar0[ka+0] : 0.f;
            sa0.y = (ka+1 < kend) ? Ar0[ka+1] : 0.f;
            sa0.z = (ka+2 < kend) ? Ar0[ka+2] : 0.f;
            sa0.w = (ka+3 < kend) ? Ar0[ka+3] : 0.f;
            sa1.x = (ka+0 < kend) ? Ar1[ka+0] : 0.f;
            sa1.y = (ka+1 < kend) ? Ar1[ka+1] : 0.f;
            sa1.z = (ka+2 < kend) ? Ar1[ka+2] : 0.f;
            sa1.w = (ka+3 < kend) ? Ar1[ka+3] : 0.f;
        }
        const int kb2 = kb + br;
        const int bc = col0 + bcq * 8;
        sb0 = make_float4(0.f, 0.f, 0.f, 0.f);
        sb1 = sb0;
        if (kb2 < kend) {
            const float* Bp = B + (size_t)kb2 * N;
            if (colFast) {
                sb0 = *(const float4*)(Bp + bc);
                sb1 = *(const float4*)(Bp + bc + 4);
            } else {
                if (bc+0 < N) sb0.x = Bp[bc+0];
                if (bc+1 < N) sb0.y = Bp[bc+1];
                if (bc+2 < N) sb0.z = Bp[bc+2];
                if (bc+3 < N) sb0.w = Bp[bc+3];
                if (bc+4 < N) sb1.x = Bp[bc+4];
                if (bc+5 < N) sb1.y = Bp[bc+5];
                if (bc+6 < N) sb1.z = Bp[bc+6];
                if (bc+7 < N) sb1.w = Bp[bc+7];
            }
        }
    };
    auto storeTile = [&](int p) {
        As[p][akq*4+0][ar]    = sa0.x;
        As[p][akq*4+1][ar]    = sa0.y;
        As[p][akq*4+2][ar]    = sa0.z;
        As[p][akq*4+3][ar]    = sa0.w;
        As[p][akq*4+0][ar+64] = sa1.x;
        As[p][akq*4+1][ar+64] = sa1.y;
        As[p][akq*4+2][ar+64] = sa1.z;
        As[p][akq*4+3][ar+64] = sa1.w;
        *(float4*)&Bs[p][br][bcq*8]     = sb0;
        *(float4*)&Bs[p][br][bcq*8 + 4] = sb1;
    };

    loadTile(kbeg);
    storeTile(0);
    __syncthreads();

    int p = 0;
    for (int k0 = kbeg; k0 < kend; k0 += 16) {
        const bool hasNext = (k0 + 16) < kend;
        if (hasNext) loadTile(k0 + 16);       // LDG overlapped with compute

        #pragma unroll
        for (int kk = 0; kk < 16; kk++) {
            float4 af0 = *(const float4*)&As[p][kk][ty*8];
            float4 af1 = *(const float4*)&As[p][kk][ty*8 + 4];
            ulonglong2 b01 = *(const ulonglong2*)&Bs[p][kk][tx*8];
            ulonglong2 b23 = *(const ulonglong2*)&Bs[p][kk][tx*8 + 4];
            ull ad;
            ad = pk2(af0.x, af0.x);
            acc[0][0]=fma2(ad,b01.x,acc[0][0]); acc[0][1]=fma2(ad,b01.y,acc[0][1]);
            acc[0][2]=fma2(ad,b23.x,acc[0][2]); acc[0][3]=fma2(ad,b23.y,acc[0][3]);
            ad = pk2(af0.y, af0.y);
            acc[1][0]=fma2(ad,b01.x,acc[1][0]); acc[1][1]=fma2(ad,b01.y,acc[1][1]);
            acc[1][2]=fma2(ad,b23.x,acc[1][2]); acc[1][3]=fma2(ad,b23.y,acc[1][3]);
            ad = pk2(af0.z, af0.z);
            acc[2][0]=fma2(ad,b01.x,acc[2][0]); acc[2][1]=fma2(ad,b01.y,acc[2][1]);
            acc[2][2]=fma2(ad,b23.x,acc[2][2]); acc[2][3]=fma2(ad,b23.y,acc[2][3]);
            ad = pk2(af0.w, af0.w);
            acc[3][0]=fma2(ad,b01.x,acc[3][0]); acc[3][1]=fma2(ad,b01.y,acc[3][1]);
            acc[3][2]=fma2(ad,b23.x,acc[3][2]); acc[3][3]=fma2(ad,b23.y,acc[3][3]);
            ad = pk2(af1.x, af1.x);
            acc[4][0]=fma2(ad,b01.x,acc[4][0]); acc[4][1]=fma2(ad,b01.y,acc[4][1]);
            acc[4][2]=fma2(ad,b23.x,acc[4][2]); acc[4][3]=fma2(ad,b23.y,acc[4][3]);
            ad = pk2(af1.y, af1.y);
            acc[5][0]=fma2(ad,b01.x,acc[5][0]); acc[5][1]=fma2(ad,b01.y,acc[5][1]);
            acc[5][2]=fma2(ad,b23.x,acc[5][2]); acc[5][3]=fma2(ad,b23.y,acc[5][3]);
            ad = pk2(af1.z, af1.z);
            acc[6][0]=fma2(ad,b01.x,acc[6][0]); acc[6][1]=fma2(ad,b01.y,acc[6][1]);
            acc[6][2]=fma2(ad,b23.x,acc[6][2]); acc[6][3]=fma2(ad,b23.y,acc[6][3]);
            ad = pk2(af1.w, af1.w);
            acc[7][0]=fma2(ad,b01.x,acc[7][0]); acc[7][1]=fma2(ad,b01.y,acc[7][1]);
            acc[7][2]=fma2(ad,b23.x,acc[7][2]); acc[7][3]=fma2(ad,b23.y,acc[7][3]);
        }
        if (hasNext) {
            storeTile(p ^ 1);                 // write OTHER buffer: no race
            __syncthreads();                  // one barrier per tile
            p ^= 1;
        }
    }

    float* Co = Cpart + (size_t)z * M * N;
    #pragma unroll
    for (int r = 0; r < 8; r++) {
        const int gr = row0 + ty*8 + r;
        if (gr >= M) continue;
        float c[8];
        upk2(acc[r][0], c[0], c[1]);
        upk2(acc[r][1], c[2], c[3]);
        upk2(acc[r][2], c[4], c[5]);
        upk2(acc[r][3], c[6], c[7]);
        const int gc = col0 + tx*8;
        if (gc + 7 < N) {
            *(float4*)&Co[(size_t)gr * N + gc]     = make_float4(c[0], c[1], c[2], c[3]);
            *(float4*)&Co[(size_t)gr * N + gc + 4] = make_float4(c[4], c[5], c[6], c[7]);
        } else {
            #pragma unroll
            for (int j = 0; j < 8; j++)
                if (gc + j < N) Co[(size_t)gr * N + gc + j] = c[j];
        }
    }
}

// ---------------- reduce split-K partials (+optional bias), any S -------
__global__ void reduce_k(float* __restrict__ out, const float* __restrict__ part,
                         int lenf4, int S, const float* __restrict__ bias, int N)
{
    int i = blockIdx.x * blockDim.x + threadIdx.x;
    if (i >= lenf4) return;
    const float4* p = (const float4*)part;
    float4 a0 = make_float4(0.f,0.f,0.f,0.f), a1 = a0, a2 = a0, a3 = a0;
    int z = 0;
    for (; z + 4 <= S; z += 4) {
        float4 t0 = p[(size_t)(z+0) * lenf4 + i];
        float4 t1 = p[(size_t)(z+1) * lenf4 + i];
        float4 t2 = p[(size_t)(z+2) * lenf4 + i];
        float4 t3 = p[(size_t)(z+3) * lenf4 + i];
        a0.x += t0.x; a0.y += t0.y; a0.z += t0.z; a0.w += t0.w;
        a1.x += t1.x; a1.y += t1.y; a1.z += t1.z; a1.w += t1.w;
        a2.x += t2.x; a2.y += t2.y; a2.z += t2.z; a2.w += t2.w;
        a3.x += t3.x; a3.y += t3.y; a3.z += t3.z; a3.w += t3.w;
    }
    for (; z < S; z++) {
        float4 t = p[(size_t)z * lenf4 + i];
        a0.x += t.x; a0.y += t.y; a0.z += t.z; a0.w += t.w;
    }
    float4 acc = make_float4(a0.x + a1.x + a2.x + a3.x,
                             a0.y + a1.y + a2.y + a3.y,
                             a0.z + a1.z + a2.z + a3.z,
                             a0.w + a1.w + a2.w + a3.w);
    if (bias) {
        int col = (i * 4) % N;      // N % 4 == 0 for all uses
        acc.x += bias[col+0]; acc.y += bias[col+1];
        acc.z += bias[col+2]; acc.w += bias[col+3];
    }
    ((float4*)out)[i] = acc;
}

// ---------------- b2 = slim_b @ proto_w_bot + proto_b  [128] ------------
__global__ void b2_kernel(const float* __restrict__ slim_b,
                          const float* __restrict__ proto_w_bot,
                          const float* __restrict__ proto_b,
                          float* __restrict__ b2)
{
    const int j = threadIdx.x;     // 128
    float acc = 0.f;
    for (int k = 0; k < DATT; k++)
        acc = fmaf(slim_b[k], proto_w_bot[(size_t)k * HH + j], acc);
    b2[j] = acc + proto_b[j];
}

// ---------------- gn = normalize_rows(attributes @ att_g) ----------------
__global__ void gn_kernel(const float* __restrict__ attrs,
                          const float* __restrict__ att_g,
                          float* __restrict__ gn) {
    __shared__ float s_attr[8][DATT];
    __shared__ float s_red[8][4];
    const int c0 = blockIdx.x * 8;
    const int t = threadIdx.x;       // 128
    const int lane = t & 31, warp = t >> 5;

    for (int i = t; i < 8 * DATT; i += 128) {
        int r = i / DATT, k = i - r * DATT;
        s_attr[r][k] = attrs[(size_t)(c0 + r) * DATT + k];
    }
    __syncthreads();

    float acc[8] = {0.f,0.f,0.f,0.f,0.f,0.f,0.f,0.f};
    for (int k = 0; k < DATT; k++) {
        float w = att_g[(size_t)k * HH + t];
        #pragma unroll
        for (int r = 0; r < 8; r++) acc[r] = fmaf(s_attr[r][k], w, acc[r]);
    }
    #pragma unroll
    for (int r = 0; r < 8; r++) {
        float sq = acc[r] * acc[r];
        #pragma unroll
        for (int o = 16; o; o >>= 1) sq += __shfl_xor_sync(0xffffffffu, sq, o);
        if (lane == 0) s_red[r][warp] = sq;
    }
    __syncthreads();
    #pragma unroll
    for (int r = 0; r < 8; r++) {
        float tot = s_red[r][0] + s_red[r][1] + s_red[r][2] + s_red[r][3];
        float inv = 1.f / fmaxf(sqrtf(tot), 1e-12f);
        gn[(size_t)(c0 + r) * HH + t] = acc[r] * inv;
    }
}

// ---------------- sim = gn @ gn^T, masked+scaled in epilogue ------------
__global__ void sim_kernel(const float* __restrict__ gn, float* __restrict__ out)
{
    __shared__ __align__(16) float As2[16][140];
    __shared__ __align__(16) float Bs[16][68];
    const int tid = threadIdx.x;
    const int row0 = blockIdx.y * 64;
    const int col0 = blockIdx.x * 64;
    const int tx = tid & 15, ty = tid >> 4;
    const int ar = tid >> 2, akq = tid & 3;

    const float* Arp = gn + (size_t)min(row0 + ar, C_CLS - 1) * HH;
    const float* Brp = gn + (size_t)min(col0 + ar, C_CLS - 1) * HH;

    ull acc[4][2];
    #pragma unroll
    for (int r = 0; r < 4; r++) { acc[r][0] = 0ull; acc[r][1] = 0ull; }

    for (int k0 = 0; k0 < HH; k0 += 16) {
        float4 av = *(const float4*)(Arp + k0 + akq*4);
        float4 bv = *(const float4*)(Brp + k0 + akq*4);
        *(float2*)&As2[akq*4+0][2*ar] = make_float2(av.x, av.x);
        *(float2*)&As2[akq*4+1][2*ar] = make_float2(av.y, av.y);
        *(float2*)&As2[akq*4+2][2*ar] = make_float2(av.z, av.z);
        *(float2*)&As2[akq*4+3][2*ar] = make_float2(av.w, av.w);
        Bs[akq*4+0][ar] = bv.x; Bs[akq*4+1][ar] = bv.y;
        Bs[akq*4+2][ar] = bv.z; Bs[akq*4+3][ar] = bv.w;
        __syncthreads();
        #pragma unroll
        for (int kk = 0; kk < 16; kk++) {
            ulonglong2 bq  = *(const ulonglong2*)&Bs[kk][tx*4];
            ulonglong2 a01 = *(const ulonglong2*)&As2[kk][ty*8];
            ulonglong2 a23 = *(const ulonglong2*)&As2[kk][ty*8+4];
            acc[0][0]=fma2(a01.x,bq.x,acc[0][0]); acc[0][1]=fma2(a01.x,bq.y,acc[0][1]);
            acc[1][0]=fma2(a01.y,bq.x,acc[1][0]); acc[1][1]=fma2(a01.y,bq.y,acc[1][1]);
            acc[2][0]=fma2(a23.x,bq.x,acc[2][0]); acc[2][1]=fma2(a23.x,bq.y,acc[2][1]);
            acc[3][0]=fma2(a23.y,bq.x,acc[3][0]); acc[3][1]=fma2(a23.y,bq.y,acc[3][1]);
        }
        __syncthreads();
    }

    #pragma unroll
    for (int r = 0; r < 4; r++) {
        const int gr = row0 + ty*4 + r;
        if (gr >= C_CLS) continue;
        float c[4];
        upk2(acc[r][0], c[0], c[1]);
        upk2(acc[r][1], c[2], c[3]);
        #pragma unroll
        for (int j = 0; j < 4; j++) {
            const int gc = col0 + tx*4 + j;
            if (gc >= C_CLS) continue;
            float s = c[j];
            out[(size_t)gr * C_CLS + gc] = (s > THRESH) ? s * TEMP : -1e30f;
        }
    }
}

// ---------------- row softmax (in place, values pre-masked+scaled) ------
__global__ void softmax_kernel(float* __restrict__ attn)
{
    __shared__ float s_red[8];
    const int t = threadIdx.x, lane = t & 31, warp = t >> 5;
    float* row = attn + (size_t)blockIdx.x * C_CLS;

    float v[4];
    float m = -1e30f;
    #pragma unroll
    for (int i = 0; i < 4; i++) {
        int c = t + i * 256;
        v[i] = (c < C_CLS) ? row[c] : -1e30f;
        m = fmaxf(m, v[i]);
    }
    #pragma unroll
    for (int o = 16; o; o >>= 1) m = fmaxf(m, __shfl_xor_sync(0xffffffffu, m, o));
    if (lane == 0) s_red[warp] = m;
    __syncthreads();
    m = s_red[0];
    #pragma unroll
    for (int w = 1; w < 8; w++) m = fmaxf(m, s_red[w]);
    __syncthreads();

    float sum = 0.f;
    #pragma unroll
    for (int i = 0; i < 4; i++) {
        float e = (v[i] > -1e29f) ? __expf(v[i] - m) : 0.f;
        v[i] = e;
        sum += e;
    }
    #pragma unroll
    for (int o = 16; o; o >>= 1) sum += __shfl_xor_sync(0xffffffffu, sum, o);
    if (lane == 0) s_red[warp] = sum;
    __syncthreads();
    float tot = 0.f;
    #pragma unroll
    for (int w = 0; w < 8; w++) tot += s_red[w];
    float inv = 1.f / tot;
    #pragma unroll
    for (int i = 0; i < 4; i++) {
        int c = t + i * 256;
        if (c < C_CLS) row[c] = v[i] * inv;
    }
}

// ---------------- relation MLP: out[b,c] = fc_b + sum_h relu(a+p)*w -----
__global__ void relation_kernel(const float* __restrict__ img_h,
                                const float* __restrict__ proto_h,
                                const float* __restrict__ fc_w,
                                const float* __restrict__ fc_b,
                                float* __restrict__ out)
{
    __shared__ __align__(16) float s_a2[64][136];  // [h][2*b] duplicated
    __shared__ __align__(16) float s_p[64][68];    // [h][c]
    __shared__ __align__(16) float s_w2[2 * HH];   // duplicated weights
    const int tid = threadIdx.x;
    const int b0 = blockIdx.y * 64;
    const int c0 = blockIdx.x * 64;
    const int tx = tid & 15;        // c: tx*4
    const int ty = tid >> 4;        // b: ty*4
    const int bl = tid >> 2;        // loader row (0..63)
    const int hq = tid & 3;         // loader h-quad group

    if (tid < HH) { float w = fc_w[tid]; s_w2[2*tid] = w; s_w2[2*tid+1] = w; }

    ull acc[4][2];
    #pragma unroll
    for (int i = 0; i < 4; i++) { acc[i][0] = 0ull; acc[i][1] = 0ull; }

    const float* arow = img_h   + (size_t)(b0 + bl) * HH;
    const float* prow = proto_h + (size_t)min(c0 + bl, C_CLS - 1) * HH;

    for (int h0 = 0; h0 < HH; h0 += 64) {
        #pragma unroll
        for (int it = 0; it < 4; it++) {
            const int hh = (hq + 4*it) * 4;
            float4 va = *(const float4*)(arow + h0 + hh);
            float4 vp = *(const float4*)(prow + h0 + hh);
            *(float2*)&s_a2[hh+0][2*bl] = make_float2(va.x, va.x);
            *(float2*)&s_a2[hh+1][2*bl] = make_float2(va.y, va.y);
            *(float2*)&s_a2[hh+2][2*bl] = make_float2(va.z, va.z);
            *(float2*)&s_a2[hh+3][2*bl] = make_float2(va.w, va.w);
            s_p[hh+0][bl] = vp.x; s_p[hh+1][bl] = vp.y;
            s_p[hh+2][bl] = vp.z; s_p[hh+3][bl] = vp.w;
        }
        __syncthreads();
        #pragma unroll 4
        for (int hh = 0; hh < 64; hh++) {
            ull w2 = *(const ull*)&s_w2[2*(h0 + hh)];
            ulonglong2 aA = *(const ulonglong2*)&s_a2[hh][ty*8];
            ulonglong2 aB = *(const ulonglong2*)&s_a2[hh][ty*8+4];
            ulonglong2 pv = *(const ulonglong2*)&s_p[hh][tx*4];
            ull av[4] = {aA.x, aA.y, aB.x, aB.y};
            #pragma unroll
            for (int i = 0; i < 4; i++) {
                acc[i][0] = fma2(relu2(add2(av[i], pv.x)), w2, acc[i][0]);
                acc[i][1] = fma2(relu2(add2(av[i], pv.y)), w2, acc[i][1]);
            }
        }
        __syncthreads();
    }

    const float bias = fc_b[0];
    #pragma unroll
    for (int i = 0; i < 4; i++) {
        const int b = b0 + ty*4 + i;
        float c[4];
        upk2(acc[i][0], c[0], c[1]);
        upk2(acc[i][1], c[2], c[3]);
        const int cc = c0 + tx*4;
        if (cc + 3 < C_CLS) {
            float4 v = make_float4(c[0] + bias, c[1] + bias, c[2] + bias, c[3] + bias);
            *(float4*)&out[(size_t)b * C_CLS + cc] = v;
        } else {
            #pragma unroll
            for (int j = 0; j < 4; j++)
                if (cc + j < C_CLS) out[(size_t)b * C_CLS + cc + j] = c[j] + bias;
        }
    }
}

// ---------------- host launch ----------------
extern "C" void kernel_launch(void* const* d_in, const int* in_sizes, int n_in,
                              void* d_out, int out_size) {
    const float* image_feats = (const float*)d_in[0];  // [2048,2048]
    const float* img_proto   = (const float*)d_in[1];  // [1000,2048]
    const float* attributes  = (const float*)d_in[2];  // [1000,312]
    const float* att_g   = (const float*)d_in[4];      // [312,128]
    const float* slim_w  = (const float*)d_in[5];      // [2048,312]
    const float* slim_b  = (const float*)d_in[6];      // [312]
    const float* img_w   = (const float*)d_in[7];      // [2048,128]
    const float* proto_w = (const float*)d_in[8];      // [624,128]
    const float* proto_b = (const float*)d_in[9];      // [1,128]
    const float* fc_w    = (const float*)d_in[10];     // [128,1]
    const float* fc_b    = (const float*)d_in[11];     // [1]
    float* out = (float*)d_out;
    const float* proto_w_bot = proto_w + (size_t)DATT * HH;

    float *gnp, *attnp, *Mp, *proto_hp, *img_hp, *W2p, *b2p, *scrA, *scrB, *scrM;
    cudaGetSymbolAddress((void**)&gnp,       g_gn);
    cudaGetSymbolAddress((void**)&attnp,     g_attn);
    cudaGetSymbolAddress((void**)&Mp,        g_M);
    cudaGetSymbolAddress((void**)&proto_hp,  g_proto_h);
    cudaGetSymbolAddress((void**)&img_hp,    g_img_h);
    cudaGetSymbolAddress((void**)&W2p,       g_W2);
    cudaGetSymbolAddress((void**)&b2p,       g_b2);
    cudaGetSymbolAddress((void**)&scrA,      g_scr_a);
    cudaGetSymbolAddress((void**)&scrB,      g_scr_b);
    cudaGetSymbolAddress((void**)&scrM,      g_scr_m);
    float* scrW2 = scrA + (size_t)32 * C_CLS * HH;   // W2 partials (4 slices)

    static cudaStream_t s1 = nullptr, s2 = nullptr, s3 = nullptr;
    static cudaEvent_t ev0 = nullptr, ev1 = nullptr, ev2 = nullptr, ev3 = nullptr;
    if (!s1) {
        cudaStreamCreateWithFlags(&s1, cudaStreamNonBlocking);
        cudaStreamCreateWithFlags(&s2, cudaStreamNonBlocking);
        cudaStreamCreateWithFlags(&s3, cudaStreamNonBlocking);
        cudaEventCreateWithFlags(&ev0, cudaEventDisableTiming);
        cudaEventCreateWithFlags(&ev1, cudaEventDisableTiming);
        cudaEventCreateWithFlags(&ev2, cudaEventDisableTiming);
        cudaEventCreateWithFlags(&ev3, cudaEventDisableTiming);
    }
    cudaStream_t s0 = 0;

    // fork
    cudaEventRecord(ev0, s0);
    cudaStreamWaitEvent(s1, ev0, 0);
    cudaStreamWaitEvent(s2, ev0, 0);
    cudaStreamWaitEvent(s3, ev0, 0);

    // ---- chain C (s1): gn -> sim -> softmax --------------------------------
    gn_kernel<<<C_CLS / 8, 128, 0, s1>>>(attributes, att_g, gnp);
    sim_kernel<<<dim3(16, 16), 256, 0, s1>>>(gnp, attnp);
    softmax_kernel<<<C_CLS, 256, 0, s1>>>(attnp);
    cudaEventRecord(ev1, s1);

    // ---- chain A (s2): img_h (split-K 24 -> 384 blocks, >=2/SM) ------------
    gemm256<<<dim3(1, 16, 24), 256, 0, s2>>>(image_feats, img_w, scrB,
                                             BB, HH, DIMG, 88);
    reduce_k<<<(BB*HH/4 + 255)/256, 256, 0, s2>>>(img_hp, scrB, BB*HH/4, 24, nullptr, HH);
    cudaEventRecord(ev2, s2);

    // ---- chain D (s3): W2 = slim_w @ proto_w_bot [2048,128] + b2 vector ----
    gemm256<<<dim3(1, 16, 4), 256, 0, s3>>>(slim_w, proto_w_bot, scrW2,
                                            DIMG, HH, DATT, 80);
    reduce_k<<<(DIMG*HH/4 + 255)/256, 256, 0, s3>>>(W2p, scrW2, DIMG*HH/4, 4, nullptr, HH);
    b2_kernel<<<1, HH, 0, s3>>>(slim_b, proto_w_bot, proto_b, b2p);
    cudaEventRecord(ev3, s3);

    // ---- chain B (s0): M_top -> M_bot (via W2) -> M -> proto_h -> relation -
    // M_top = attributes @ proto_w_top, slices 0..3
    gemm256<<<dim3(1, 8, 4), 256, 0, s0>>>(attributes, proto_w, scrM,
                                           C_CLS, HH, DATT, 80);
    // M_bot = img_proto @ W2, slices 4..27 (24-way split-K over 2048 -> 192 blocks)
    cudaStreamWaitEvent(s0, ev3, 0);
    gemm256<<<dim3(1, 8, 24), 256, 0, s0>>>(img_proto, W2p,
                                            scrM + 4 * (size_t)C_CLS * HH,
                                            C_CLS, HH, DIMG, 88);
    // M = sum(28 slices) + b2  (b2 = slim_b@proto_w_bot + proto_b)
    reduce_k<<<(C_CLS*HH/4 + 255)/256, 256, 0, s0>>>(Mp, scrM, C_CLS*HH/4, 28, b2p, HH);

    // proto_h = attn @ M (split-K 32; b2/proto_b folded via softmax row-sum=1)
    cudaStreamWaitEvent(s0, ev1, 0);
    gemm256<<<dim3(1, 8, 32), 256, 0, s0>>>(attnp, Mp, scrA, C_CLS, HH, C_CLS, 32);
    reduce_k<<<(C_CLS*HH/4 + 255)/256, 256, 0, s0>>>(proto_hp, scrA, C_CLS*HH/4, 32, nullptr, HH);

    // ---- join: relation ----------------------------------------------------
    cudaStreamWaitEvent(s0, ev2, 0);
    relation_kernel<<<dim3(16, 32), 256, 0, s0>>>(img_hp, proto_hp, fc_w, fc_b, out);
}